// round 9
// baseline (speedup 1.0000x reference)
#include <cuda_runtime.h>
#include <cuda_bf16.h>
#include <stdint.h>
#include <math.h>

#define BB 64
#define TT 512
#define DD 512
#define HH 512
#define G4H 2048  // 4*H

typedef unsigned long long ull;
typedef unsigned int u32;

// -------- device scratch (no cudaMalloc allowed) --------
__device__ float g_Zx[2][TT * BB][G4H];          // x-projection + bias
__device__ float g_h[2][2][HH][BB];              // hidden state [dir][pingpong][k][b]
__device__ volatile unsigned g_phase[2];
__device__ unsigned g_arrive[2];
__device__ __nv_bfloat16 g_Ahi[TT * BB][DD];     // x reordered (m=t*B+b), bf16 hi
__device__ __nv_bfloat16 g_Alo[TT * BB][DD];     // bf16 lo
__device__ __nv_bfloat16 g_WT[2][2][G4H][DD];    // W[:512] transposed, [dir][hi/lo][n][k]

// ---- scalar helpers ----
#define FMA2(d, a, b, c) \
    asm("fma.rn.f32x2 %0, %1, %2, %3;" : "=l"(d) : "l"(a), "l"(b), "l"(c))
#define DUP2(d, x) \
    asm("mov.b64 %0, {%1, %1};" : "=l"(d) : "r"(__float_as_uint(x)))
#define UNPK2(lo, hi, v) \
    asm("mov.b64 {%0, %1}, %2;" : "=r"(lo), "=r"(hi) : "l"(v))
#define CP_ASYNC16(smem_addr, gptr) \
    asm volatile("cp.async.cg.shared.global [%0], [%1], 16;" :: "r"(smem_addr), "l"(gptr))
#define CP_COMMIT()  asm volatile("cp.async.commit_group;")
#define CP_WAIT0()   asm volatile("cp.async.wait_group 0;" ::: "memory")

__device__ __forceinline__ float fsigmoid(float x) { return 1.f / (1.f + __expf(-x)); }

// warp-level bf16 MMA, m16n8k16, f32 accumulate (base PTX, works on sm_103)
__device__ __forceinline__ void mma16816(float* c, u32 a0, u32 a1, u32 a2, u32 a3,
                                         u32 b0, u32 b1) {
    asm volatile(
        "mma.sync.aligned.m16n8k16.row.col.f32.bf16.bf16.f32 "
        "{%0,%1,%2,%3}, {%4,%5,%6,%7}, {%8,%9}, {%0,%1,%2,%3};"
        : "+f"(c[0]), "+f"(c[1]), "+f"(c[2]), "+f"(c[3])
        : "r"(a0), "r"(a1), "r"(a2), "r"(a3), "r"(b0), "r"(b1));
}

// -------- prep: split x into bf16 hi/lo, reordered m = t*B + b --------
__global__ void prep_ab(const float* __restrict__ x) {
    int idx = blockIdx.x * blockDim.x + threadIdx.x;   // over TT*BB*DD
    int d = idx & 511;
    int m = idx >> 9;
    int t = m >> 6, b = m & 63;
    float v = x[((size_t)b * TT + t) * DD + d];
    __nv_bfloat16 hi = __float2bfloat16(v);
    float lo = v - __bfloat162float(hi);
    g_Ahi[m][d] = hi;
    g_Alo[m][d] = __float2bfloat16(lo);
}

// -------- prep: split+transpose W[:512] rows; also init h/barrier state --------
__global__ void prep_w(const float* __restrict__ Wfw, const float* __restrict__ Wbw) {
    int idx = blockIdx.x * blockDim.x + threadIdx.x;   // over 2*G4H*DD = 2.1M
    if (idx < 2 * G4H * DD) {
        int k = idx & 511;
        int n = (idx >> 9) & 2047;
        int dir = idx >> 20;
        const float* Wm = dir ? Wbw : Wfw;
        float v = Wm[(size_t)k * G4H + n];
        __nv_bfloat16 hi = __float2bfloat16(v);
        float lo = v - __bfloat162float(hi);
        g_WT[dir][0][n][k] = hi;
        g_WT[dir][1][n][k] = __float2bfloat16(lo);
    }
    if (idx < 2 * 2 * HH * BB) (&g_h[0][0][0][0])[idx] = 0.f;
    if (idx == 0) { g_phase[0] = 0; g_phase[1] = 0; g_arrive[0] = 0; g_arrive[1] = 0; }
}

// -------- mma.sync x-projection GEMM: 3x bf16-split --------
// grid (N/128=16, M/128=256, 2), 256 threads = 8 warps (4 m x 2 n), warp tile 32x64.
// Fragments loaded straight from global with explicit per-lane addressing:
//   A (row-major [m][k]):  a0=(g,2tg) a1=(g+8,2tg) a2=(g,2tg+8) a3=(g+8,2tg+8)
//   B (col-major = g_WT[n][k]): b0=(k=2tg,n=g) b1=(k=2tg+8,n=g)
//   C: c0=(g,2tg) c1=(g,2tg+1) c2=(g+8,2tg) c3=(g+8,2tg+1)
__global__ void __launch_bounds__(256)
pregemm_mma(const float* __restrict__ bfw, const float* __restrict__ bbw) {
    int dir = blockIdx.z;
    int n0 = blockIdx.x * 128;
    int m0 = blockIdx.y * 128;
    const float* bias = dir ? bbw : bfw;

    int tid  = threadIdx.x;
    int warp = tid >> 5;
    int lane = tid & 31;
    int g  = lane >> 2;      // 0..7
    int tg = lane & 3;       // 0..3

    int wm = (warp & 3) * 32;   // warp m-origin within tile (4 warps)
    int wn = (warp >> 2) * 64;  // warp n-origin within tile (2 warps)

    float acc[2][8][4];
#pragma unroll
    for (int i = 0; i < 2; i++)
#pragma unroll
        for (int j = 0; j < 8; j++)
#pragma unroll
            for (int q = 0; q < 4; q++) acc[i][j][q] = 0.f;

    const __nv_bfloat16* Ah = &g_Ahi[m0 + wm + g][2 * tg];
    const __nv_bfloat16* Al = &g_Alo[m0 + wm + g][2 * tg];
    const __nv_bfloat16* Bh = &g_WT[dir][0][n0 + wn + g][2 * tg];
    const __nv_bfloat16* Bl = &g_WT[dir][1][n0 + wn + g][2 * tg];

#pragma unroll 1
    for (int k0 = 0; k0 < DD; k0 += 16) {
        // A fragments for 2 m-tiles (16 rows apart), hi and lo splits
        u32 ah[2][4], al[2][4];
#pragma unroll
        for (int mt = 0; mt < 2; mt++) {
            const __nv_bfloat16* p = Ah + (size_t)mt * 16 * DD + k0;
            const __nv_bfloat16* q = Al + (size_t)mt * 16 * DD + k0;
            ah[mt][0] = *(const u32*)(p);
            ah[mt][1] = *(const u32*)(p + 8 * DD);
            ah[mt][2] = *(const u32*)(p + 8);
            ah[mt][3] = *(const u32*)(p + 8 * DD + 8);
            al[mt][0] = *(const u32*)(q);
            al[mt][1] = *(const u32*)(q + 8 * DD);
            al[mt][2] = *(const u32*)(q + 8);
            al[mt][3] = *(const u32*)(q + 8 * DD + 8);
        }
#pragma unroll
        for (int nt = 0; nt < 8; nt++) {
            const __nv_bfloat16* pb = Bh + (size_t)nt * 8 * DD + k0;
            const __nv_bfloat16* qb = Bl + (size_t)nt * 8 * DD + k0;
            u32 bh0 = *(const u32*)(pb);
            u32 bh1 = *(const u32*)(pb + 8);
            u32 bl0 = *(const u32*)(qb);
            u32 bl1 = *(const u32*)(qb + 8);
#pragma unroll
            for (int mt = 0; mt < 2; mt++) {
                mma16816(acc[mt][nt], ah[mt][0], ah[mt][1], ah[mt][2], ah[mt][3], bh0, bh1);
                mma16816(acc[mt][nt], ah[mt][0], ah[mt][1], ah[mt][2], ah[mt][3], bl0, bl1);
                mma16816(acc[mt][nt], al[mt][0], al[mt][1], al[mt][2], al[mt][3], bh0, bh1);
            }
        }
    }

    // epilogue: bias + store (float2 per row-pair fragment)
#pragma unroll
    for (int nt = 0; nt < 8; nt++) {
        int col = n0 + wn + nt * 8 + 2 * tg;
        float b0 = bias[col], b1 = bias[col + 1];
#pragma unroll
        for (int mt = 0; mt < 2; mt++) {
            int row0 = m0 + wm + mt * 16 + g;
            float2 v0 = make_float2(acc[mt][nt][0] + b0, acc[mt][nt][1] + b1);
            float2 v1 = make_float2(acc[mt][nt][2] + b0, acc[mt][nt][3] + b1);
            *(float2*)&g_Zx[dir][row0][col]     = v0;
            *(float2*)&g_Zx[dir][row0 + 8][col] = v1;
        }
    }
}

// -------- per-direction grid barrier --------
__device__ __forceinline__ void grid_barrier(int dir, unsigned target) {
    __syncthreads();
    if (threadIdx.x == 0) {
        __threadfence();
        unsigned old = atomicAdd(&g_arrive[dir], 1);
        if (old == 63) {
            g_arrive[dir] = 0;
            __threadfence();
            g_phase[dir] = target;
        } else {
            while (g_phase[dir] < target) { }
            __threadfence();
        }
    }
    __syncthreads();
}

// -------- persistent recurrent kernel (unchanged from R6) --------
#define SM_W   (512 * 32)
#define SM_H   (512 * 64)
#define SMEM_FLOATS (SM_W + SM_H)

__global__ void __launch_bounds__(512, 1)
lstm_persist(const float* __restrict__ Wfw, const float* __restrict__ Wbw,
             float* __restrict__ out) {
    extern __shared__ float smf[];
    float* w_s = smf;
    float* h_s = smf + SM_W;

    int dir = blockIdx.y;
    int hb  = blockIdx.x;
    int h0  = hb * 8;
    const float* Wm = dir ? Wbw : Wfw;

    int tid = threadIdx.x;
    int kg  = tid >> 6;
    int wt  = tid & 63;
    int ty  = wt >> 2;
    int tx  = wt & 3;

    for (int idx = tid; idx < 4096; idx += 512) {
        int row = idx >> 3;
        int c4  = (idx & 7) * 4;
        int g   = c4 >> 3;
        int hl  = c4 & 7;
        *(float4*)&w_s[row * 32 + c4] =
            *(const float4*)(Wm + (size_t)(DD + row) * G4H + g * 512 + h0 + hl);
    }

    int pb = tid >> 3, phl = tid & 7;
    float c_reg = 0.f;

    const float* wp  = &w_s[(kg * 64) * 32 + tx * 8];
    const float* hsp = &h_s[(kg * 64) * 64 + ty * 4];
    float* zout = h_s + kg * (64 * 33);

    unsigned h_s_u32 = (unsigned)__cvta_generic_to_shared(h_s);

    __syncthreads();

#pragma unroll 1
    for (int t = 0; t < TT; ++t) {
        int tin = dir ? (TT - 1 - t) : t;
        int buf = t & 1;

        {
            const float* hg = &g_h[dir][buf][0][0];
#pragma unroll
            for (int j = 0; j < 16; ++j) {
                int c = tid + j * 512;
                CP_ASYNC16(h_s_u32 + c * 16, hg + c * 4);
            }
            CP_COMMIT();
        }

        float rzx[4];
        {
            const float* zp = &g_Zx[dir][tin * BB + pb][h0 + phl];
#pragma unroll
            for (int g = 0; g < 4; g++) rzx[g] = zp[g * 512];
        }

        CP_WAIT0();
        __syncthreads();

        ull acc[4][4];
#pragma unroll
        for (int i = 0; i < 4; i++)
#pragma unroll
            for (int p = 0; p < 4; p++) acc[i][p] = 0ull;

#pragma unroll 4
        for (int kk = 0; kk < 64; ++kk) {
            float4 hv = *(const float4*)(hsp + kk * 64);
            ull a0, a1, a2, a3;
            DUP2(a0, hv.x);
            DUP2(a1, hv.y);
            DUP2(a2, hv.z);
            DUP2(a3, hv.w);
            const float* wrow = wp + kk * 32;
            ulonglong2 bq0 = *(const ulonglong2*)(wrow);
            ulonglong2 bq1 = *(const ulonglong2*)(wrow + 4);
            FMA2(acc[0][0], a0, bq0.x, acc[0][0]);
            FMA2(acc[0][1], a0, bq0.y, acc[0][1]);
            FMA2(acc[0][2], a0, bq1.x, acc[0][2]);
            FMA2(acc[0][3], a0, bq1.y, acc[0][3]);
            FMA2(acc[1][0], a1, bq0.x, acc[1][0]);
            FMA2(acc[1][1], a1, bq0.y, acc[1][1]);
            FMA2(acc[1][2], a1, bq1.x, acc[1][2]);
            FMA2(acc[1][3], a1, bq1.y, acc[1][3]);
            FMA2(acc[2][0], a2, bq0.x, acc[2][0]);
            FMA2(acc[2][1], a2, bq0.y, acc[2][1]);
            FMA2(acc[2][2], a2, bq1.x, acc[2][2]);
            FMA2(acc[2][3], a2, bq1.y, acc[2][3]);
            FMA2(acc[3][0], a3, bq0.x, acc[3][0]);
            FMA2(acc[3][1], a3, bq0.y, acc[3][1]);
            FMA2(acc[3][2], a3, bq1.x, acc[3][2]);
            FMA2(acc[3][3], a3, bq1.y, acc[3][3]);
        }

        __syncthreads();
#pragma unroll
        for (int i = 0; i < 4; i++) {
            float* row = &zout[(ty * 4 + i) * 33 + tx * 8];
#pragma unroll
            for (int p = 0; p < 4; p++) {
                unsigned lo, hi;
                UNPK2(lo, hi, acc[i][p]);
                row[p * 2 + 0] = __uint_as_float(lo);
                row[p * 2 + 1] = __uint_as_float(hi);
            }
        }
        __syncthreads();

        {
            int b = pb, hl = phl;
            float zi = rzx[0], zj = rzx[1], zf = rzx[2], zo = rzx[3];
#pragma unroll
            for (int g2 = 0; g2 < 8; g2++) {
                const float* zp = &h_s[g2 * (64 * 33) + b * 33];
                zi += zp[0 + hl];
                zj += zp[8 + hl];
                zf += zp[16 + hl];
                zo += zp[24 + hl];
            }

            float ig = fsigmoid(zi);
            float jg = tanhf(zj);
            float fg = fsigmoid(zf + 1.f);
            float og = fsigmoid(zo);

            float cnew = fg * c_reg + ig * jg;
            float hnew = og * tanhf(cnew);
            c_reg = cnew;

            g_h[dir][buf ^ 1][h0 + hl][b] = hnew;
            out[((size_t)b * TT + tin) * (2 * HH) + dir * HH + h0 + hl] = hnew;
        }

        grid_barrier(dir, (unsigned)(t + 1));
    }
}

extern "C" void kernel_launch(void* const* d_in, const int* in_sizes, int n_in,
                              void* d_out, int out_size) {
    const float* x   = (const float*)d_in[0];
    const float* Wfw = (const float*)d_in[1];
    const float* bfw = (const float*)d_in[2];
    const float* Wbw = (const float*)d_in[3];
    const float* bbw = (const float*)d_in[4];
    float* out = (float*)d_out;

    static int attr_done = 0;
    if (!attr_done) {
        cudaFuncSetAttribute(lstm_persist, cudaFuncAttributeMaxDynamicSharedMemorySize,
                             SMEM_FLOATS * sizeof(float));
        attr_done = 1;
    }

    // bf16 hi/lo splits of x (reordered) and W[:512] (transposed); h/barrier init
    prep_ab<<<(TT * BB * DD) / 256, 256>>>(x);
    prep_w<<<(2 * G4H * DD + 255) / 256, 256>>>(Wfw, Wbw);

    // mma.sync x-projection for both directions (bias folded in at epilogue)
    pregemm_mma<<<dim3(G4H / 128, (TT * BB) / 128, 2), 256>>>(bfw, bbw);

    // persistent recurrent kernel: 512 steps, both directions
    lstm_persist<<<dim3(64, 2), 512, SMEM_FLOATS * sizeof(float)>>>(Wfw, Wbw, out);
}

// round 10
// speedup vs baseline: 1.2450x; 1.2450x over previous
#include <cuda_runtime.h>
#include <cuda_bf16.h>
#include <stdint.h>
#include <math.h>

#define BB 64
#define TT 512
#define DD 512
#define HH 512
#define G4H 2048  // 4*H

typedef unsigned long long ull;
typedef unsigned int u32;

// -------- device scratch (no cudaMalloc allowed) --------
__device__ float g_Zx[2][TT * BB][G4H];          // x-projection + bias
__device__ float g_h[2][2][HH][BB];              // hidden state [dir][pingpong][k][b]
__device__ volatile unsigned g_phase[2];
__device__ unsigned g_arrive[2];
__device__ __nv_bfloat16 g_Ahi[TT * BB][DD];     // x reordered (m=t*B+b), bf16 hi
__device__ __nv_bfloat16 g_Alo[TT * BB][DD];     // bf16 lo
__device__ __nv_bfloat16 g_WT[2][2][G4H][DD];    // W[:512] transposed, [dir][hi/lo][n][k]

// ---- scalar helpers ----
#define FMA2(d, a, b, c) \
    asm("fma.rn.f32x2 %0, %1, %2, %3;" : "=l"(d) : "l"(a), "l"(b), "l"(c))
#define DUP2(d, x) \
    asm("mov.b64 %0, {%1, %1};" : "=l"(d) : "r"(__float_as_uint(x)))
#define UNPK2(lo, hi, v) \
    asm("mov.b64 {%0, %1}, %2;" : "=r"(lo), "=r"(hi) : "l"(v))
#define CP_ASYNC16(smem_addr, gptr) \
    asm volatile("cp.async.cg.shared.global [%0], [%1], 16;" :: "r"(smem_addr), "l"(gptr))
#define CP_COMMIT()  asm volatile("cp.async.commit_group;")
#define CP_WAIT0()   asm volatile("cp.async.wait_group 0;" ::: "memory")
#define CP_WAIT1()   asm volatile("cp.async.wait_group 1;" ::: "memory")

__device__ __forceinline__ float fsigmoid(float x) { return 1.f / (1.f + __expf(-x)); }

// warp-level bf16 MMA, m16n8k16, f32 accumulate (base PTX, works on sm_103)
__device__ __forceinline__ void mma16816(float* c, const u32* a, u32 b0, u32 b1) {
    asm volatile(
        "mma.sync.aligned.m16n8k16.row.col.f32.bf16.bf16.f32 "
        "{%0,%1,%2,%3}, {%4,%5,%6,%7}, {%8,%9}, {%0,%1,%2,%3};"
        : "+f"(c[0]), "+f"(c[1]), "+f"(c[2]), "+f"(c[3])
        : "r"(a[0]), "r"(a[1]), "r"(a[2]), "r"(a[3]), "r"(b0), "r"(b1));
}

#define LDSM_X4(r0, r1, r2, r3, addr) \
    asm volatile("ldmatrix.sync.aligned.m8n8.x4.shared.b16 {%0,%1,%2,%3}, [%4];" \
                 : "=r"(r0), "=r"(r1), "=r"(r2), "=r"(r3) : "r"(addr))

__device__ __forceinline__ u32 smem_u32(const void* p) {
    u32 a;
    asm("{ .reg .u64 t; cvta.to.shared.u64 t, %1; cvt.u32.u64 %0, t; }" : "=r"(a) : "l"(p));
    return a;
}

// -------- prep: split x into bf16 hi/lo, reordered m = t*B + b --------
__global__ void prep_ab(const float* __restrict__ x) {
    int idx = blockIdx.x * blockDim.x + threadIdx.x;
    int d = idx & 511;
    int m = idx >> 9;
    int t = m >> 6, b = m & 63;
    float v = x[((size_t)b * TT + t) * DD + d];
    __nv_bfloat16 hi = __float2bfloat16(v);
    float lo = v - __bfloat162float(hi);
    g_Ahi[m][d] = hi;
    g_Alo[m][d] = __float2bfloat16(lo);
}

// -------- prep: split+transpose W[:512] rows; also init h/barrier state --------
__global__ void prep_w(const float* __restrict__ Wfw, const float* __restrict__ Wbw) {
    int idx = blockIdx.x * blockDim.x + threadIdx.x;
    if (idx < 2 * G4H * DD) {
        int k = idx & 511;
        int n = (idx >> 9) & 2047;
        int dir = idx >> 20;
        const float* Wm = dir ? Wbw : Wfw;
        float v = Wm[(size_t)k * G4H + n];
        __nv_bfloat16 hi = __float2bfloat16(v);
        float lo = v - __bfloat162float(hi);
        g_WT[dir][0][n][k] = hi;
        g_WT[dir][1][n][k] = __float2bfloat16(lo);
    }
    if (idx < 2 * 2 * HH * BB) (&g_h[0][0][0][0])[idx] = 0.f;
    if (idx == 0) { g_phase[0] = 0; g_phase[1] = 0; g_arrive[0] = 0; g_arrive[1] = 0; }
}

// -------- mma.sync + ldmatrix x-projection GEMM: 3x bf16-split --------
// 128x128 CTA tile, 256 thr = 8 warps (4m x 2n), warp tile 32x64, k-chunk 32, dbl-buffered.
// smem tiles padded to 40 bf16/row (80B stride -> conflict-free ldmatrix).
#define PK      40                      // padded k per row (elems)
#define TILE_B  (128 * PK * 2)          // one split tile bytes = 10240
#define PG_SMEM (8 * TILE_B)            // 2 bufs x 2 splits x (A + B) = 81920

__global__ void __launch_bounds__(256, 2)
pregemm_mma(const float* __restrict__ bfw, const float* __restrict__ bbw) {
    extern __shared__ char smc[];
    u32 smb = smem_u32(smc);
    // layout: A[buf][split] at (buf*2+split)*TILE_B ; B at 4*TILE_B + same
    int dir = blockIdx.z;
    int n0 = blockIdx.x * 128;
    int m0 = blockIdx.y * 128;
    const float* bias = dir ? bbw : bfw;

    int tid  = threadIdx.x;
    int warp = tid >> 5;
    int lane = tid & 31;
    int g  = lane >> 2;
    int tg = lane & 3;

    int wm = (warp & 3) * 32;
    int wn = (warp >> 2) * 64;

    // global load mapping: idx -> (row, kcol16B)
    int lrow = 0, lkcol = 0;
    {
        int idx = tid;          // + it*256
        lrow  = idx >> 2;       // 0..63 (+128 for it=1)
        lkcol = (idx & 3) * 8;  // bf16 elems
    }
    const __nv_bfloat16* gsrc[4];
    gsrc[0] = &g_Ahi[m0][0];
    gsrc[1] = &g_Alo[m0][0];
    gsrc[2] = &g_WT[dir][0][n0][0];
    gsrc[3] = &g_WT[dir][1][n0][0];

    // ldmatrix per-thread offsets
    int rowA  = lane & 15;
    int koffA = (lane >> 4) * 8;
    int rowB  = (lane & 7) + ((lane >> 4) << 3);
    int koffB = ((lane >> 3) & 1) * 8;
    u32 aoff = (u32)(((wm + rowA) * PK + koffA) * 2);
    u32 boff = (u32)(((wn + rowB) * PK + koffB) * 2);

    float acc[2][8][4];
#pragma unroll
    for (int i = 0; i < 2; i++)
#pragma unroll
        for (int j = 0; j < 8; j++)
#pragma unroll
            for (int q = 0; q < 4; q++) acc[i][j][q] = 0.f;

    // ---- chunk loader: 4 tiles x 2 iters of 16B cp.async per thread ----
    auto load_chunk = [&](int c, int buf) {
#pragma unroll
        for (int tile = 0; tile < 4; tile++) {
            u32 base = smb + (tile < 2 ? 0 : 4 * TILE_B) + (buf * 2 + (tile & 1)) * TILE_B;
#pragma unroll
            for (int it = 0; it < 2; it++) {
                int row = lrow + it * 64;
                const __nv_bfloat16* src = gsrc[tile] + (size_t)row * DD + c * 32 + lkcol;
                u32 dst = base + (u32)((row * PK + lkcol) * 2);
                CP_ASYNC16(dst, src);
            }
        }
        CP_COMMIT();
    };

    load_chunk(0, 0);

#pragma unroll 1
    for (int c = 0; c < 16; ++c) {
        int buf = c & 1;
        if (c < 15) { load_chunk(c + 1, buf ^ 1); CP_WAIT1(); }
        else        { CP_WAIT0(); }
        __syncthreads();

        u32 aBase0 = smb + (buf * 2 + 0) * TILE_B + aoff;   // Ahi
        u32 aBase1 = smb + (buf * 2 + 1) * TILE_B + aoff;   // Alo
        u32 bBase0 = smb + 4 * TILE_B + (buf * 2 + 0) * TILE_B + boff;  // Bhi
        u32 bBase1 = smb + 4 * TILE_B + (buf * 2 + 1) * TILE_B + boff;  // Blo

#pragma unroll
        for (int k16 = 0; k16 < 2; ++k16) {
            u32 kb = (u32)(k16 * 32);    // 16 bf16 = 32B
            u32 ah[2][4], al[2][4];
#pragma unroll
            for (int mt = 0; mt < 2; mt++) {
                LDSM_X4(ah[mt][0], ah[mt][1], ah[mt][2], ah[mt][3],
                        aBase0 + kb + mt * (16 * PK * 2));
                LDSM_X4(al[mt][0], al[mt][1], al[mt][2], al[mt][3],
                        aBase1 + kb + mt * (16 * PK * 2));
            }
#pragma unroll
            for (int ng = 0; ng < 4; ng++) {
                u32 bh[4], bl[4];
                LDSM_X4(bh[0], bh[1], bh[2], bh[3], bBase0 + kb + ng * (16 * PK * 2));
                LDSM_X4(bl[0], bl[1], bl[2], bl[3], bBase1 + kb + ng * (16 * PK * 2));
#pragma unroll
                for (int mt = 0; mt < 2; mt++) {
                    mma16816(acc[mt][ng * 2],     ah[mt], bh[0], bh[1]);
                    mma16816(acc[mt][ng * 2 + 1], ah[mt], bh[2], bh[3]);
                    mma16816(acc[mt][ng * 2],     ah[mt], bl[0], bl[1]);
                    mma16816(acc[mt][ng * 2 + 1], ah[mt], bl[2], bl[3]);
                    mma16816(acc[mt][ng * 2],     al[mt], bh[0], bh[1]);
                    mma16816(acc[mt][ng * 2 + 1], al[mt], bh[2], bh[3]);
                }
            }
        }
        __syncthreads();
    }

    // epilogue: bias + store (float2 per row-pair fragment)
#pragma unroll
    for (int nt = 0; nt < 8; nt++) {
        int col = n0 + wn + nt * 8 + 2 * tg;
        float b0 = bias[col], b1 = bias[col + 1];
#pragma unroll
        for (int mt = 0; mt < 2; mt++) {
            int row0 = m0 + wm + mt * 16 + g;
            float2 v0 = make_float2(acc[mt][nt][0] + b0, acc[mt][nt][1] + b1);
            float2 v1 = make_float2(acc[mt][nt][2] + b0, acc[mt][nt][3] + b1);
            *(float2*)&g_Zx[dir][row0][col]     = v0;
            *(float2*)&g_Zx[dir][row0 + 8][col] = v1;
        }
    }
}

// -------- per-direction grid barrier --------
__device__ __forceinline__ void grid_barrier(int dir, unsigned target) {
    __syncthreads();
    if (threadIdx.x == 0) {
        __threadfence();
        unsigned old = atomicAdd(&g_arrive[dir], 1);
        if (old == 63) {
            g_arrive[dir] = 0;
            __threadfence();
            g_phase[dir] = target;
        } else {
            while (g_phase[dir] < target) { }
            __threadfence();
        }
    }
    __syncthreads();
}

// -------- persistent recurrent kernel (unchanged) --------
#define SM_W   (512 * 32)
#define SM_H   (512 * 64)
#define SMEM_FLOATS (SM_W + SM_H)

__global__ void __launch_bounds__(512, 1)
lstm_persist(const float* __restrict__ Wfw, const float* __restrict__ Wbw,
             float* __restrict__ out) {
    extern __shared__ float smf[];
    float* w_s = smf;
    float* h_s = smf + SM_W;

    int dir = blockIdx.y;
    int hb  = blockIdx.x;
    int h0  = hb * 8;
    const float* Wm = dir ? Wbw : Wfw;

    int tid = threadIdx.x;
    int kg  = tid >> 6;
    int wt  = tid & 63;
    int ty  = wt >> 2;
    int tx  = wt & 3;

    for (int idx = tid; idx < 4096; idx += 512) {
        int row = idx >> 3;
        int c4  = (idx & 7) * 4;
        int g   = c4 >> 3;
        int hl  = c4 & 7;
        *(float4*)&w_s[row * 32 + c4] =
            *(const float4*)(Wm + (size_t)(DD + row) * G4H + g * 512 + h0 + hl);
    }

    int pb = tid >> 3, phl = tid & 7;
    float c_reg = 0.f;

    const float* wp  = &w_s[(kg * 64) * 32 + tx * 8];
    const float* hsp = &h_s[(kg * 64) * 64 + ty * 4];
    float* zout = h_s + kg * (64 * 33);

    unsigned h_s_u32 = (unsigned)__cvta_generic_to_shared(h_s);

    __syncthreads();

#pragma unroll 1
    for (int t = 0; t < TT; ++t) {
        int tin = dir ? (TT - 1 - t) : t;
        int buf = t & 1;

        {
            const float* hg = &g_h[dir][buf][0][0];
#pragma unroll
            for (int j = 0; j < 16; ++j) {
                int c = tid + j * 512;
                CP_ASYNC16(h_s_u32 + c * 16, hg + c * 4);
            }
            CP_COMMIT();
        }

        float rzx[4];
        {
            const float* zp = &g_Zx[dir][tin * BB + pb][h0 + phl];
#pragma unroll
            for (int g = 0; g < 4; g++) rzx[g] = zp[g * 512];
        }

        CP_WAIT0();
        __syncthreads();

        ull acc[4][4];
#pragma unroll
        for (int i = 0; i < 4; i++)
#pragma unroll
            for (int p = 0; p < 4; p++) acc[i][p] = 0ull;

#pragma unroll 4
        for (int kk = 0; kk < 64; ++kk) {
            float4 hv = *(const float4*)(hsp + kk * 64);
            ull a0, a1, a2, a3;
            DUP2(a0, hv.x);
            DUP2(a1, hv.y);
            DUP2(a2, hv.z);
            DUP2(a3, hv.w);
            const float* wrow = wp + kk * 32;
            ulonglong2 bq0 = *(const ulonglong2*)(wrow);
            ulonglong2 bq1 = *(const ulonglong2*)(wrow + 4);
            FMA2(acc[0][0], a0, bq0.x, acc[0][0]);
            FMA2(acc[0][1], a0, bq0.y, acc[0][1]);
            FMA2(acc[0][2], a0, bq1.x, acc[0][2]);
            FMA2(acc[0][3], a0, bq1.y, acc[0][3]);
            FMA2(acc[1][0], a1, bq0.x, acc[1][0]);
            FMA2(acc[1][1], a1, bq0.y, acc[1][1]);
            FMA2(acc[1][2], a1, bq1.x, acc[1][2]);
            FMA2(acc[1][3], a1, bq1.y, acc[1][3]);
            FMA2(acc[2][0], a2, bq0.x, acc[2][0]);
            FMA2(acc[2][1], a2, bq0.y, acc[2][1]);
            FMA2(acc[2][2], a2, bq1.x, acc[2][2]);
            FMA2(acc[2][3], a2, bq1.y, acc[2][3]);
            FMA2(acc[3][0], a3, bq0.x, acc[3][0]);
            FMA2(acc[3][1], a3, bq0.y, acc[3][1]);
            FMA2(acc[3][2], a3, bq1.x, acc[3][2]);
            FMA2(acc[3][3], a3, bq1.y, acc[3][3]);
        }

        __syncthreads();
#pragma unroll
        for (int i = 0; i < 4; i++) {
            float* row = &zout[(ty * 4 + i) * 33 + tx * 8];
#pragma unroll
            for (int p = 0; p < 4; p++) {
                unsigned lo, hi;
                UNPK2(lo, hi, acc[i][p]);
                row[p * 2 + 0] = __uint_as_float(lo);
                row[p * 2 + 1] = __uint_as_float(hi);
            }
        }
        __syncthreads();

        {
            int b = pb, hl = phl;
            float zi = rzx[0], zj = rzx[1], zf = rzx[2], zo = rzx[3];
#pragma unroll
            for (int g2 = 0; g2 < 8; g2++) {
                const float* zp = &h_s[g2 * (64 * 33) + b * 33];
                zi += zp[0 + hl];
                zj += zp[8 + hl];
                zf += zp[16 + hl];
                zo += zp[24 + hl];
            }

            float ig = fsigmoid(zi);
            float jg = tanhf(zj);
            float fg = fsigmoid(zf + 1.f);
            float og = fsigmoid(zo);

            float cnew = fg * c_reg + ig * jg;
            float hnew = og * tanhf(cnew);
            c_reg = cnew;

            g_h[dir][buf ^ 1][h0 + hl][b] = hnew;
            out[((size_t)b * TT + tin) * (2 * HH) + dir * HH + h0 + hl] = hnew;
        }

        grid_barrier(dir, (unsigned)(t + 1));
    }
}

extern "C" void kernel_launch(void* const* d_in, const int* in_sizes, int n_in,
                              void* d_out, int out_size) {
    const float* x   = (const float*)d_in[0];
    const float* Wfw = (const float*)d_in[1];
    const float* bfw = (const float*)d_in[2];
    const float* Wbw = (const float*)d_in[3];
    const float* bbw = (const float*)d_in[4];
    float* out = (float*)d_out;

    static int attr_done = 0;
    if (!attr_done) {
        cudaFuncSetAttribute(lstm_persist, cudaFuncAttributeMaxDynamicSharedMemorySize,
                             SMEM_FLOATS * sizeof(float));
        cudaFuncSetAttribute(pregemm_mma, cudaFuncAttributeMaxDynamicSharedMemorySize,
                             PG_SMEM);
        attr_done = 1;
    }

    prep_ab<<<(TT * BB * DD) / 256, 256>>>(x);
    prep_w<<<(2 * G4H * DD + 255) / 256, 256>>>(Wfw, Wbw);

    pregemm_mma<<<dim3(G4H / 128, (TT * BB) / 128, 2), 256, PG_SMEM>>>(bfw, bbw);

    lstm_persist<<<dim3(64, 2), 512, SMEM_FLOATS * sizeof(float)>>>(Wfw, Wbw, out);
}

// round 11
// speedup vs baseline: 1.6165x; 1.2984x over previous
#include <cuda_runtime.h>
#include <cuda_bf16.h>
#include <stdint.h>
#include <math.h>

#define BB 64
#define TT 512
#define DD 512
#define HH 512
#define G4H 2048  // 4*H

typedef unsigned long long ull;
typedef unsigned int u32;

// -------- device scratch (no cudaMalloc allowed) --------
__device__ float g_Zx[2][TT * BB][G4H];          // x-projection + bias
__device__ volatile unsigned g_phase[2];
__device__ unsigned g_arrive[2];
__device__ __nv_bfloat16 g_Ahi[TT * BB][DD];     // x reordered (m=t*B+b), bf16 hi
__device__ __nv_bfloat16 g_Alo[TT * BB][DD];     // bf16 lo
__device__ __nv_bfloat16 g_WT[2][2][G4H][DD];    // W[:512] transposed [dir][hi/lo][n][k]
__device__ __nv_bfloat16 g_WhT[2][2][G4H][DD];   // W[512:] transposed [dir][hi/lo][n][k]
__device__ __nv_bfloat16 g_hb[2][2][2][BB][HH];  // h state [dir][buf][hi/lo][b][k]

// ---- helpers ----
#define CP_ASYNC16(smem_addr, gptr) \
    asm volatile("cp.async.cg.shared.global [%0], [%1], 16;" :: "r"(smem_addr), "l"(gptr))
#define CP_COMMIT()  asm volatile("cp.async.commit_group;")
#define CP_WAIT0()   asm volatile("cp.async.wait_group 0;" ::: "memory")
#define CP_WAIT1()   asm volatile("cp.async.wait_group 1;" ::: "memory")

__device__ __forceinline__ float fsigmoid(float x) { return 1.f / (1.f + __expf(-x)); }

__device__ __forceinline__ void mma16816(float* c, const u32* a, u32 b0, u32 b1) {
    asm volatile(
        "mma.sync.aligned.m16n8k16.row.col.f32.bf16.bf16.f32 "
        "{%0,%1,%2,%3}, {%4,%5,%6,%7}, {%8,%9}, {%0,%1,%2,%3};"
        : "+f"(c[0]), "+f"(c[1]), "+f"(c[2]), "+f"(c[3])
        : "r"(a[0]), "r"(a[1]), "r"(a[2]), "r"(a[3]), "r"(b0), "r"(b1));
}

#define LDSM_X4(r0, r1, r2, r3, addr) \
    asm volatile("ldmatrix.sync.aligned.m8n8.x4.shared.b16 {%0,%1,%2,%3}, [%4];" \
                 : "=r"(r0), "=r"(r1), "=r"(r2), "=r"(r3) : "r"(addr))

__device__ __forceinline__ u32 smem_u32(const void* p) {
    u32 a;
    asm("{ .reg .u64 t; cvta.to.shared.u64 t, %1; cvt.u32.u64 %0, t; }" : "=r"(a) : "l"(p));
    return a;
}

// -------- prep: split x into bf16 hi/lo, reordered m = t*B + b --------
__global__ void prep_ab(const float* __restrict__ x) {
    int idx = blockIdx.x * blockDim.x + threadIdx.x;
    int d = idx & 511;
    int m = idx >> 9;
    int t = m >> 6, b = m & 63;
    float v = x[((size_t)b * TT + t) * DD + d];
    __nv_bfloat16 hi = __float2bfloat16(v);
    float lo = v - __bfloat162float(hi);
    g_Ahi[m][d] = hi;
    g_Alo[m][d] = __float2bfloat16(lo);
}

// -------- prep: split+transpose W (both halves); zero h state; init barrier --------
__global__ void prep_w(const float* __restrict__ Wfw, const float* __restrict__ Wbw) {
    int idx = blockIdx.x * blockDim.x + threadIdx.x;   // over 4*G4H*DD
    if (idx < 2 * G4H * DD) {
        int k = idx & 511;
        int n = (idx >> 9) & 2047;
        int dir = idx >> 20;
        const float* Wm = dir ? Wbw : Wfw;
        float v = Wm[(size_t)k * G4H + n];
        __nv_bfloat16 hi = __float2bfloat16(v);
        float lo = v - __bfloat162float(hi);
        g_WT[dir][0][n][k] = hi;
        g_WT[dir][1][n][k] = __float2bfloat16(lo);
    } else if (idx < 4 * G4H * DD) {
        int i2 = idx - 2 * G4H * DD;
        int k = i2 & 511;
        int n = (i2 >> 9) & 2047;
        int dir = i2 >> 20;
        const float* Wm = dir ? Wbw : Wfw;
        float v = Wm[(size_t)(DD + k) * G4H + n];
        __nv_bfloat16 hi = __float2bfloat16(v);
        float lo = v - __bfloat162float(hi);
        g_WhT[dir][0][n][k] = hi;
        g_WhT[dir][1][n][k] = __float2bfloat16(lo);
    }
    if (idx < 2 * 2 * 2 * BB * HH)
        (&g_hb[0][0][0][0][0])[idx] = __float2bfloat16(0.f);
    if (idx == 0) { g_phase[0] = 0; g_phase[1] = 0; g_arrive[0] = 0; g_arrive[1] = 0; }
}

// -------- mma.sync + ldmatrix x-projection GEMM (unchanged from R10) --------
#define PK      40
#define TILE_B  (128 * PK * 2)
#define PG_SMEM (8 * TILE_B)

__global__ void __launch_bounds__(256, 2)
pregemm_mma(const float* __restrict__ bfw, const float* __restrict__ bbw) {
    extern __shared__ char smc[];
    u32 smb = smem_u32(smc);
    int dir = blockIdx.z;
    int n0 = blockIdx.x * 128;
    int m0 = blockIdx.y * 128;
    const float* bias = dir ? bbw : bfw;

    int tid  = threadIdx.x;
    int warp = tid >> 5;
    int lane = tid & 31;
    int g  = lane >> 2;
    int tg = lane & 3;

    int wm = (warp & 3) * 32;
    int wn = (warp >> 2) * 64;

    int lrow  = tid >> 2;
    int lkcol = (tid & 3) * 8;
    const __nv_bfloat16* gsrc[4];
    gsrc[0] = &g_Ahi[m0][0];
    gsrc[1] = &g_Alo[m0][0];
    gsrc[2] = &g_WT[dir][0][n0][0];
    gsrc[3] = &g_WT[dir][1][n0][0];

    int rowA  = lane & 15;
    int koffA = (lane >> 4) * 8;
    int rowB  = (lane & 7) + ((lane >> 4) << 3);
    int koffB = ((lane >> 3) & 1) * 8;
    u32 aoff = (u32)(((wm + rowA) * PK + koffA) * 2);
    u32 boff = (u32)(((wn + rowB) * PK + koffB) * 2);

    float acc[2][8][4];
#pragma unroll
    for (int i = 0; i < 2; i++)
#pragma unroll
        for (int j = 0; j < 8; j++)
#pragma unroll
            for (int q = 0; q < 4; q++) acc[i][j][q] = 0.f;

    auto load_chunk = [&](int c, int buf) {
#pragma unroll
        for (int tile = 0; tile < 4; tile++) {
            u32 base = smb + (tile < 2 ? 0 : 4 * TILE_B) + (buf * 2 + (tile & 1)) * TILE_B;
#pragma unroll
            for (int it = 0; it < 2; it++) {
                int row = lrow + it * 64;
                const __nv_bfloat16* src = gsrc[tile] + (size_t)row * DD + c * 32 + lkcol;
                u32 dst = base + (u32)((row * PK + lkcol) * 2);
                CP_ASYNC16(dst, src);
            }
        }
        CP_COMMIT();
    };

    load_chunk(0, 0);

#pragma unroll 1
    for (int c = 0; c < 16; ++c) {
        int buf = c & 1;
        if (c < 15) { load_chunk(c + 1, buf ^ 1); CP_WAIT1(); }
        else        { CP_WAIT0(); }
        __syncthreads();

        u32 aBase0 = smb + (buf * 2 + 0) * TILE_B + aoff;
        u32 aBase1 = smb + (buf * 2 + 1) * TILE_B + aoff;
        u32 bBase0 = smb + 4 * TILE_B + (buf * 2 + 0) * TILE_B + boff;
        u32 bBase1 = smb + 4 * TILE_B + (buf * 2 + 1) * TILE_B + boff;

#pragma unroll
        for (int k16 = 0; k16 < 2; ++k16) {
            u32 kb = (u32)(k16 * 32);
            u32 ah[2][4], al[2][4];
#pragma unroll
            for (int mt = 0; mt < 2; mt++) {
                LDSM_X4(ah[mt][0], ah[mt][1], ah[mt][2], ah[mt][3],
                        aBase0 + kb + mt * (16 * PK * 2));
                LDSM_X4(al[mt][0], al[mt][1], al[mt][2], al[mt][3],
                        aBase1 + kb + mt * (16 * PK * 2));
            }
#pragma unroll
            for (int ng = 0; ng < 4; ng++) {
                u32 bh[4], bl[4];
                LDSM_X4(bh[0], bh[1], bh[2], bh[3], bBase0 + kb + ng * (16 * PK * 2));
                LDSM_X4(bl[0], bl[1], bl[2], bl[3], bBase1 + kb + ng * (16 * PK * 2));
#pragma unroll
                for (int mt = 0; mt < 2; mt++) {
                    mma16816(acc[mt][ng * 2],     ah[mt], bh[0], bh[1]);
                    mma16816(acc[mt][ng * 2 + 1], ah[mt], bh[2], bh[3]);
                    mma16816(acc[mt][ng * 2],     ah[mt], bl[0], bl[1]);
                    mma16816(acc[mt][ng * 2 + 1], ah[mt], bl[2], bl[3]);
                    mma16816(acc[mt][ng * 2],     al[mt], bh[0], bh[1]);
                    mma16816(acc[mt][ng * 2 + 1], al[mt], bh[2], bh[3]);
                }
            }
        }
        __syncthreads();
    }

#pragma unroll
    for (int nt = 0; nt < 8; nt++) {
        int col = n0 + wn + nt * 8 + 2 * tg;
        float b0 = bias[col], b1 = bias[col + 1];
#pragma unroll
        for (int mt = 0; mt < 2; mt++) {
            int row0 = m0 + wm + mt * 16 + g;
            float2 v0 = make_float2(acc[mt][nt][0] + b0, acc[mt][nt][1] + b1);
            float2 v1 = make_float2(acc[mt][nt][2] + b0, acc[mt][nt][3] + b1);
            *(float2*)&g_Zx[dir][row0][col]     = v0;
            *(float2*)&g_Zx[dir][row0 + 8][col] = v1;
        }
    }
}

// -------- per-direction grid barrier --------
__device__ __forceinline__ void grid_barrier(int dir, unsigned target) {
    __syncthreads();
    if (threadIdx.x == 0) {
        __threadfence();
        unsigned old = atomicAdd(&g_arrive[dir], 1);
        if (old == 63) {
            g_arrive[dir] = 0;
            __threadfence();
            g_phase[dir] = target;
        } else {
            while (g_phase[dir] < target) { }
            __threadfence();
        }
    }
    __syncthreads();
}

// -------- persistent recurrent kernel: bf16-split mma.sync --------
// grid (64 h-blocks, 2 dirs), 512 thr = 16 warps = 4 m-tiles(16) x 4 k-splits(128).
// CTA output: z[64 b x 32 gathered cols (4 gates x 8 h)].
// smem: A hi/lo [64][520] staged per step + B hi/lo [32][520] resident; z aliases A.
#define PKH       520
#define A_SPLIT_B (64 * PKH * 2)      // 66560
#define B_SPLIT_B (32 * PKH * 2)      // 33280
#define OFF_ALO   A_SPLIT_B
#define OFF_BHI   (2 * A_SPLIT_B)
#define OFF_BLO   (2 * A_SPLIT_B + B_SPLIT_B)
#define PERSIST_SMEM (2 * A_SPLIT_B + 2 * B_SPLIT_B)   // 199680

__global__ void __launch_bounds__(512, 1)
lstm_persist(float* __restrict__ out) {
    extern __shared__ char smc[];
    u32 smb = smem_u32(smc);
    float* z_s = (float*)smc;                 // [4][64][34] alias of A region

    int dir = blockIdx.y;
    int hb  = blockIdx.x;
    int h0  = hb * 8;

    int tid  = threadIdx.x;
    int warp = tid >> 5;
    int lane = tid & 31;
    int mt = warp & 3;          // m-tile: batch rows mt*16..
    int kg = warp >> 2;         // k-split: k in [kg*128, kg*128+128)
    int wm = mt * 16;

    // ---- load resident B slice (32 gathered n-rows x 512 k x 2 splits) ----
    for (int c = tid; c < 4096; c += 512) {
        int split = c >> 11;
        int r  = (c & 2047) >> 6;       // 0..31  (gate*8 + hl)
        int ch = c & 63;
        int gate = r >> 3, hl = r & 7;
        const __nv_bfloat16* src = &g_WhT[dir][split][gate * 512 + h0 + hl][ch * 8];
        u32 dst = smb + OFF_BHI + split * B_SPLIT_B + (u32)(r * PKH * 2 + ch * 16);
        CP_ASYNC16(dst, src);
    }
    CP_COMMIT();

    // fragment offsets (mappings verified in pregemm)
    int rowA  = lane & 15;
    int koffA = (lane >> 4) * 8;
    int rowB  = (lane & 7) + ((lane >> 4) << 3);
    int koffB = ((lane >> 3) & 1) * 8;
    u32 aoff = (u32)(((wm + rowA) * PKH + koffA) * 2);
    u32 boff = (u32)((rowB * PKH + koffB) * 2);

    int pb = tid >> 3, phl = tid & 7;   // pointwise: 1 (b,h) per thread
    float c_reg = 0.f;

    int zg = lane >> 2;       // c-fragment row within m16
    int ztg = lane & 3;       // c-fragment col pair

    CP_WAIT0();
    __syncthreads();

#pragma unroll 1
    for (int t = 0; t < TT; ++t) {
        int tin = dir ? (TT - 1 - t) : t;
        int buf = t & 1;

        // ---- stage h hi/lo (64x512 bf16 each) into smem [b][520] ----
        {
            const __nv_bfloat16* hg = &g_hb[dir][buf][0][0][0];
#pragma unroll
            for (int j = 0; j < 16; ++j) {
                int c = tid + j * 512;          // 0..8191
                int split = c >> 12;
                int r  = (c & 4095) >> 6;
                int ch = c & 63;
                u32 dst = smb + split * A_SPLIT_B + (u32)(r * PKH * 2 + ch * 16);
                CP_ASYNC16(dst, hg + (size_t)split * BB * HH + r * 512 + ch * 8);
            }
            CP_COMMIT();
        }

        // prefetch Zx for this step
        float rzx[4];
        {
            const float* zp = &g_Zx[dir][tin * BB + pb][h0 + phl];
#pragma unroll
            for (int g = 0; g < 4; g++) rzx[g] = zp[g * 512];
        }

        CP_WAIT0();
        __syncthreads();

        float acc[4][4];
#pragma unroll
        for (int i = 0; i < 4; i++)
#pragma unroll
            for (int q = 0; q < 4; q++) acc[i][q] = 0.f;

        u32 aBaseH = smb + aoff;
        u32 aBaseL = smb + OFF_ALO + aoff;
        u32 bBaseH = smb + OFF_BHI + boff;
        u32 bBaseL = smb + OFF_BLO + boff;
        int kbase = kg * 128;

#pragma unroll
        for (int k16 = 0; k16 < 8; ++k16) {
            u32 kb = (u32)((kbase + k16 * 16) * 2);
            u32 ah[4], al[4];
            LDSM_X4(ah[0], ah[1], ah[2], ah[3], aBaseH + kb);
            LDSM_X4(al[0], al[1], al[2], al[3], aBaseL + kb);
#pragma unroll
            for (int g2 = 0; g2 < 2; ++g2) {
                u32 gofs = (u32)(g2 * 16 * PKH * 2);
                u32 bh[4], bl[4];
                LDSM_X4(bh[0], bh[1], bh[2], bh[3], bBaseH + kb + gofs);
                LDSM_X4(bl[0], bl[1], bl[2], bl[3], bBaseL + kb + gofs);
                mma16816(acc[g2 * 2],     ah, bh[0], bh[1]);
                mma16816(acc[g2 * 2 + 1], ah, bh[2], bh[3]);
                mma16816(acc[g2 * 2],     ah, bl[0], bl[1]);
                mma16816(acc[g2 * 2 + 1], ah, bl[2], bl[3]);
                mma16816(acc[g2 * 2],     al, bh[0], bh[1]);
                mma16816(acc[g2 * 2 + 1], al, bh[2], bh[3]);
            }
        }

        // ---- stash z partials (alias into A region; all LDSM done) ----
        __syncthreads();
#pragma unroll
        for (int gate = 0; gate < 4; gate++) {
            int col = gate * 8 + 2 * ztg;
            *(float2*)&z_s[((kg * 64) + wm + zg) * 34 + col] =
                make_float2(acc[gate][0], acc[gate][1]);
            *(float2*)&z_s[((kg * 64) + wm + zg + 8) * 34 + col] =
                make_float2(acc[gate][2], acc[gate][3]);
        }
        __syncthreads();

        // ---- pointwise LSTM update ----
        {
            int b = pb, hl = phl;
            float zi = rzx[0], zj = rzx[1], zf = rzx[2], zo = rzx[3];
#pragma unroll
            for (int g2 = 0; g2 < 4; g2++) {
                const float* zp = &z_s[(g2 * 64 + b) * 34];
                zi += zp[0 + hl];
                zj += zp[8 + hl];
                zf += zp[16 + hl];
                zo += zp[24 + hl];
            }

            float ig = fsigmoid(zi);
            float jg = tanhf(zj);
            float fg = fsigmoid(zf + 1.f);
            float og = fsigmoid(zo);

            float cnew = fg * c_reg + ig * jg;
            float hnew = og * tanhf(cnew);
            c_reg = cnew;

            __nv_bfloat16 hhi = __float2bfloat16(hnew);
            __nv_bfloat16 hlo = __float2bfloat16(hnew - __bfloat162float(hhi));
            g_hb[dir][buf ^ 1][0][b][h0 + hl] = hhi;
            g_hb[dir][buf ^ 1][1][b][h0 + hl] = hlo;
            out[((size_t)b * TT + tin) * (2 * HH) + dir * HH + h0 + hl] = hnew;
        }

        grid_barrier(dir, (unsigned)(t + 1));
    }
}

extern "C" void kernel_launch(void* const* d_in, const int* in_sizes, int n_in,
                              void* d_out, int out_size) {
    const float* x   = (const float*)d_in[0];
    const float* Wfw = (const float*)d_in[1];
    const float* bfw = (const float*)d_in[2];
    const float* Wbw = (const float*)d_in[3];
    const float* bbw = (const float*)d_in[4];
    float* out = (float*)d_out;

    static int attr_done = 0;
    if (!attr_done) {
        cudaFuncSetAttribute(lstm_persist, cudaFuncAttributeMaxDynamicSharedMemorySize,
                             PERSIST_SMEM);
        cudaFuncSetAttribute(pregemm_mma, cudaFuncAttributeMaxDynamicSharedMemorySize,
                             PG_SMEM);
        attr_done = 1;
    }

    prep_ab<<<(TT * BB * DD) / 256, 256>>>(x);
    prep_w<<<(4 * G4H * DD + 255) / 256, 256>>>(Wfw, Wbw);

    pregemm_mma<<<dim3(G4H / 128, (TT * BB) / 128, 2), 256, PG_SMEM>>>(bfw, bbw);

    lstm_persist<<<dim3(64, 2), 512, PERSIST_SMEM>>>(out);
}

// round 12
// speedup vs baseline: 1.7037x; 1.0539x over previous
#include <cuda_runtime.h>
#include <cuda_bf16.h>
#include <stdint.h>
#include <math.h>

#define BB 64
#define TT 512
#define DD 512
#define HH 512
#define G4H 2048  // 4*H

typedef unsigned long long ull;
typedef unsigned int u32;

// -------- device scratch (no cudaMalloc allowed) --------
__device__ float g_Zx[2][TT * BB][G4H];          // x-projection + bias
__device__ volatile unsigned g_phase[2];
__device__ unsigned g_arrive[2];
__device__ __nv_bfloat16 g_Ahi[TT * BB][DD];     // x reordered (m=t*B+b), bf16 hi
__device__ __nv_bfloat16 g_Alo[TT * BB][DD];     // bf16 lo
__device__ __nv_bfloat16 g_WT[2][2][G4H][DD];    // W[:512] transposed [dir][hi/lo][n][k]
__device__ __nv_bfloat16 g_WhT[2][2][G4H][DD];   // W[512:] transposed [dir][hi/lo][n][k]
__device__ __nv_bfloat16 g_hb[2][2][2][BB][HH];  // h state [dir][buf][hi/lo][b][k]

// ---- helpers ----
#define CP_ASYNC16(smem_addr, gptr) \
    asm volatile("cp.async.cg.shared.global [%0], [%1], 16;" :: "r"(smem_addr), "l"(gptr))
#define CP_COMMIT()  asm volatile("cp.async.commit_group;")
#define CP_WAIT0()   asm volatile("cp.async.wait_group 0;" ::: "memory")
#define CP_WAIT1()   asm volatile("cp.async.wait_group 1;" ::: "memory")

// fast sigmoid/tanh: MUFU.EX2 + MUFU.RCP only (NaN-safe at +-inf of exp)
__device__ __forceinline__ float fsig(float x)  { return __fdividef(1.f, 1.f + __expf(-x)); }
__device__ __forceinline__ float ftanh(float x) { return __fdividef(2.f, 1.f + __expf(-2.f * x)) - 1.f; }
// slow-but-exact sigmoid for pregemm-free paths (unused in hot loop)
__device__ __forceinline__ float fsigmoid(float x) { return 1.f / (1.f + __expf(-x)); }

__device__ __forceinline__ void mma16816(float* c, const u32* a, u32 b0, u32 b1) {
    asm volatile(
        "mma.sync.aligned.m16n8k16.row.col.f32.bf16.bf16.f32 "
        "{%0,%1,%2,%3}, {%4,%5,%6,%7}, {%8,%9}, {%0,%1,%2,%3};"
        : "+f"(c[0]), "+f"(c[1]), "+f"(c[2]), "+f"(c[3])
        : "r"(a[0]), "r"(a[1]), "r"(a[2]), "r"(a[3]), "r"(b0), "r"(b1));
}

#define LDSM_X4(r0, r1, r2, r3, addr) \
    asm volatile("ldmatrix.sync.aligned.m8n8.x4.shared.b16 {%0,%1,%2,%3}, [%4];" \
                 : "=r"(r0), "=r"(r1), "=r"(r2), "=r"(r3) : "r"(addr))

__device__ __forceinline__ u32 smem_u32(const void* p) {
    u32 a;
    asm("{ .reg .u64 t; cvta.to.shared.u64 t, %1; cvt.u32.u64 %0, t; }" : "=r"(a) : "l"(p));
    return a;
}

// -------- prep: split x into bf16 hi/lo, reordered m = t*B + b --------
__global__ void prep_ab(const float* __restrict__ x) {
    int idx = blockIdx.x * blockDim.x + threadIdx.x;
    int d = idx & 511;
    int m = idx >> 9;
    int t = m >> 6, b = m & 63;
    float v = x[((size_t)b * TT + t) * DD + d];
    __nv_bfloat16 hi = __float2bfloat16(v);
    float lo = v - __bfloat162float(hi);
    g_Ahi[m][d] = hi;
    g_Alo[m][d] = __float2bfloat16(lo);
}

// -------- prep: split+transpose W (both halves); zero h state; init barrier --------
__global__ void prep_w(const float* __restrict__ Wfw, const float* __restrict__ Wbw) {
    int idx = blockIdx.x * blockDim.x + threadIdx.x;   // over 4*G4H*DD
    if (idx < 2 * G4H * DD) {
        int k = idx & 511;
        int n = (idx >> 9) & 2047;
        int dir = idx >> 20;
        const float* Wm = dir ? Wbw : Wfw;
        float v = Wm[(size_t)k * G4H + n];
        __nv_bfloat16 hi = __float2bfloat16(v);
        float lo = v - __bfloat162float(hi);
        g_WT[dir][0][n][k] = hi;
        g_WT[dir][1][n][k] = __float2bfloat16(lo);
    } else if (idx < 4 * G4H * DD) {
        int i2 = idx - 2 * G4H * DD;
        int k = i2 & 511;
        int n = (i2 >> 9) & 2047;
        int dir = i2 >> 20;
        const float* Wm = dir ? Wbw : Wfw;
        float v = Wm[(size_t)(DD + k) * G4H + n];
        __nv_bfloat16 hi = __float2bfloat16(v);
        float lo = v - __bfloat162float(hi);
        g_WhT[dir][0][n][k] = hi;
        g_WhT[dir][1][n][k] = __float2bfloat16(lo);
    }
    if (idx < 2 * 2 * 2 * BB * HH)
        (&g_hb[0][0][0][0][0])[idx] = __float2bfloat16(0.f);
    if (idx == 0) { g_phase[0] = 0; g_phase[1] = 0; g_arrive[0] = 0; g_arrive[1] = 0; }
}

// -------- mma.sync + ldmatrix x-projection GEMM (unchanged, verified) --------
#define PK      40
#define TILE_B  (128 * PK * 2)
#define PG_SMEM (8 * TILE_B)

__global__ void __launch_bounds__(256, 2)
pregemm_mma(const float* __restrict__ bfw, const float* __restrict__ bbw) {
    extern __shared__ char smc[];
    u32 smb = smem_u32(smc);
    int dir = blockIdx.z;
    int n0 = blockIdx.x * 128;
    int m0 = blockIdx.y * 128;
    const float* bias = dir ? bbw : bfw;

    int tid  = threadIdx.x;
    int warp = tid >> 5;
    int lane = tid & 31;
    int g  = lane >> 2;
    int tg = lane & 3;

    int wm = (warp & 3) * 32;
    int wn = (warp >> 2) * 64;

    int lrow  = tid >> 2;
    int lkcol = (tid & 3) * 8;
    const __nv_bfloat16* gsrc[4];
    gsrc[0] = &g_Ahi[m0][0];
    gsrc[1] = &g_Alo[m0][0];
    gsrc[2] = &g_WT[dir][0][n0][0];
    gsrc[3] = &g_WT[dir][1][n0][0];

    int rowA  = lane & 15;
    int koffA = (lane >> 4) * 8;
    int rowB  = (lane & 7) + ((lane >> 4) << 3);
    int koffB = ((lane >> 3) & 1) * 8;
    u32 aoff = (u32)(((wm + rowA) * PK + koffA) * 2);
    u32 boff = (u32)(((wn + rowB) * PK + koffB) * 2);

    float acc[2][8][4];
#pragma unroll
    for (int i = 0; i < 2; i++)
#pragma unroll
        for (int j = 0; j < 8; j++)
#pragma unroll
            for (int q = 0; q < 4; q++) acc[i][j][q] = 0.f;

    auto load_chunk = [&](int c, int buf) {
#pragma unroll
        for (int tile = 0; tile < 4; tile++) {
            u32 base = smb + (tile < 2 ? 0 : 4 * TILE_B) + (buf * 2 + (tile & 1)) * TILE_B;
#pragma unroll
            for (int it = 0; it < 2; it++) {
                int row = lrow + it * 64;
                const __nv_bfloat16* src = gsrc[tile] + (size_t)row * DD + c * 32 + lkcol;
                u32 dst = base + (u32)((row * PK + lkcol) * 2);
                CP_ASYNC16(dst, src);
            }
        }
        CP_COMMIT();
    };

    load_chunk(0, 0);

#pragma unroll 1
    for (int c = 0; c < 16; ++c) {
        int buf = c & 1;
        if (c < 15) { load_chunk(c + 1, buf ^ 1); CP_WAIT1(); }
        else        { CP_WAIT0(); }
        __syncthreads();

        u32 aBase0 = smb + (buf * 2 + 0) * TILE_B + aoff;
        u32 aBase1 = smb + (buf * 2 + 1) * TILE_B + aoff;
        u32 bBase0 = smb + 4 * TILE_B + (buf * 2 + 0) * TILE_B + boff;
        u32 bBase1 = smb + 4 * TILE_B + (buf * 2 + 1) * TILE_B + boff;

#pragma unroll
        for (int k16 = 0; k16 < 2; ++k16) {
            u32 kb = (u32)(k16 * 32);
            u32 ah[2][4], al[2][4];
#pragma unroll
            for (int mt = 0; mt < 2; mt++) {
                LDSM_X4(ah[mt][0], ah[mt][1], ah[mt][2], ah[mt][3],
                        aBase0 + kb + mt * (16 * PK * 2));
                LDSM_X4(al[mt][0], al[mt][1], al[mt][2], al[mt][3],
                        aBase1 + kb + mt * (16 * PK * 2));
            }
#pragma unroll
            for (int ng = 0; ng < 4; ng++) {
                u32 bh[4], bl[4];
                LDSM_X4(bh[0], bh[1], bh[2], bh[3], bBase0 + kb + ng * (16 * PK * 2));
                LDSM_X4(bl[0], bl[1], bl[2], bl[3], bBase1 + kb + ng * (16 * PK * 2));
#pragma unroll
                for (int mt = 0; mt < 2; mt++) {
                    mma16816(acc[mt][ng * 2],     ah[mt], bh[0], bh[1]);
                    mma16816(acc[mt][ng * 2 + 1], ah[mt], bh[2], bh[3]);
                    mma16816(acc[mt][ng * 2],     ah[mt], bl[0], bl[1]);
                    mma16816(acc[mt][ng * 2 + 1], ah[mt], bl[2], bl[3]);
                    mma16816(acc[mt][ng * 2],     al[mt], bh[0], bh[1]);
                    mma16816(acc[mt][ng * 2 + 1], al[mt], bh[2], bh[3]);
                }
            }
        }
        __syncthreads();
    }

#pragma unroll
    for (int nt = 0; nt < 8; nt++) {
        int col = n0 + wn + nt * 8 + 2 * tg;
        float b0 = bias[col], b1 = bias[col + 1];
#pragma unroll
        for (int mt = 0; mt < 2; mt++) {
            int row0 = m0 + wm + mt * 16 + g;
            float2 v0 = make_float2(acc[mt][nt][0] + b0, acc[mt][nt][1] + b1);
            float2 v1 = make_float2(acc[mt][nt][2] + b0, acc[mt][nt][3] + b1);
            *(float2*)&g_Zx[dir][row0][col]     = v0;
            *(float2*)&g_Zx[dir][row0 + 8][col] = v1;
        }
    }
}

// -------- per-direction grid barrier --------
__device__ __forceinline__ void grid_barrier(int dir, unsigned target) {
    __syncthreads();
    if (threadIdx.x == 0) {
        __threadfence();
        unsigned old = atomicAdd(&g_arrive[dir], 1);
        if (old == 63) {
            g_arrive[dir] = 0;
            __threadfence();
            g_phase[dir] = target;
        } else {
            while (g_phase[dir] < target) { }
            __threadfence();
        }
    }
    __syncthreads();
}

// -------- persistent recurrent kernel: bf16-split mma.sync, group-split staging --------
#define PKH       520
#define A_SPLIT_B (64 * PKH * 2)      // 66560
#define B_SPLIT_B (32 * PKH * 2)      // 33280
#define OFF_ALO   A_SPLIT_B
#define OFF_BHI   (2 * A_SPLIT_B)
#define OFF_BLO   (2 * A_SPLIT_B + B_SPLIT_B)
#define PERSIST_SMEM (2 * A_SPLIT_B + 2 * B_SPLIT_B)   // 199680

__global__ void __launch_bounds__(512, 1)
lstm_persist(float* __restrict__ out) {
    extern __shared__ char smc[];
    u32 smb = smem_u32(smc);
    float* z_s = (float*)smc;                 // [4][64][34] alias of A region

    int dir = blockIdx.y;
    int hb  = blockIdx.x;
    int h0  = hb * 8;

    int tid  = threadIdx.x;
    int warp = tid >> 5;
    int lane = tid & 31;
    int mt = warp & 3;          // m-tile: batch rows mt*16..
    int kg = warp >> 2;         // k-split: k in [kg*128, kg*128+128)
    int wm = mt * 16;
    int grp = tid >> 8;         // staging/compute group: 0 -> k[0:256], 1 -> k[256:512]
    int gt  = tid & 255;

    // ---- load resident B slice (32 gathered n-rows x 512 k x 2 splits) ----
    for (int c = tid; c < 4096; c += 512) {
        int split = c >> 11;
        int r  = (c & 2047) >> 6;
        int ch = c & 63;
        int gate = r >> 3, hl = r & 7;
        const __nv_bfloat16* src = &g_WhT[dir][split][gate * 512 + h0 + hl][ch * 8];
        u32 dst = smb + OFF_BHI + split * B_SPLIT_B + (u32)(r * PKH * 2 + ch * 16);
        CP_ASYNC16(dst, src);
    }
    CP_COMMIT();

    // fragment offsets (mappings verified)
    int rowA  = lane & 15;
    int koffA = (lane >> 4) * 8;
    int rowB  = (lane & 7) + ((lane >> 4) << 3);
    int koffB = ((lane >> 3) & 1) * 8;
    u32 aoff = (u32)(((wm + rowA) * PKH + koffA) * 2);
    u32 boff = (u32)((rowB * PKH + koffB) * 2);

    int pb = tid >> 3, phl = tid & 7;   // pointwise: 1 (b,h) per thread
    float c_reg = 0.f;

    int zg = lane >> 2;
    int ztg = lane & 3;

    CP_WAIT0();
    __syncthreads();

#pragma unroll 1
    for (int t = 0; t < TT; ++t) {
        int tin = dir ? (TT - 1 - t) : t;
        int buf = t & 1;

        // ---- stage own k-half of h hi/lo into smem [b][520] ----
        {
            const __nv_bfloat16* hg = &g_hb[dir][buf][0][0][0];
#pragma unroll
            for (int j = 0; j < 16; ++j) {
                int c = gt + j * 256;            // 0..4095 within this group's half
                int split = c >> 11;
                int rem = c & 2047;
                int r  = rem >> 5;               // 0..63 (batch)
                int ch = rem & 31;               // 8-elem chunk within k-half
                u32 dst = smb + split * A_SPLIT_B +
                          (u32)(r * (PKH * 2) + (grp * 256 + ch * 8) * 2);
                CP_ASYNC16(dst, hg + (size_t)split * BB * HH + r * 512 + grp * 256 + ch * 8);
            }
            CP_COMMIT();
        }

        // prefetch Zx for this step (hidden behind staging wait)
        float rzx[4];
        {
            const float* zp = &g_Zx[dir][tin * BB + pb][h0 + phl];
#pragma unroll
            for (int g = 0; g < 4; g++) rzx[g] = zp[g * 512];
        }

        CP_WAIT0();
        asm volatile("bar.sync %0, 256;" :: "r"(1 + grp) : "memory");

        float acc[4][4];
#pragma unroll
        for (int i = 0; i < 4; i++)
#pragma unroll
            for (int q = 0; q < 4; q++) acc[i][q] = 0.f;

        u32 aBaseH = smb + aoff;
        u32 aBaseL = smb + OFF_ALO + aoff;
        u32 bBaseH = smb + OFF_BHI + boff;
        u32 bBaseL = smb + OFF_BLO + boff;
        int kbase = kg * 128;

#pragma unroll
        for (int k16 = 0; k16 < 8; ++k16) {
            u32 kb = (u32)((kbase + k16 * 16) * 2);
            u32 ah[4], al[4];
            LDSM_X4(ah[0], ah[1], ah[2], ah[3], aBaseH + kb);
            LDSM_X4(al[0], al[1], al[2], al[3], aBaseL + kb);
#pragma unroll
            for (int g2 = 0; g2 < 2; ++g2) {
                u32 gofs = (u32)(g2 * 16 * PKH * 2);
                u32 bh[4], bl[4];
                LDSM_X4(bh[0], bh[1], bh[2], bh[3], bBaseH + kb + gofs);
                LDSM_X4(bl[0], bl[1], bl[2], bl[3], bBaseL + kb + gofs);
                mma16816(acc[g2 * 2],     ah, bh[0], bh[1]);
                mma16816(acc[g2 * 2 + 1], ah, bh[2], bh[3]);
                mma16816(acc[g2 * 2],     ah, bl[0], bl[1]);
                mma16816(acc[g2 * 2 + 1], ah, bl[2], bl[3]);
                mma16816(acc[g2 * 2],     al, bh[0], bh[1]);
                mma16816(acc[g2 * 2 + 1], al, bh[2], bh[3]);
            }
        }

        // ---- stash z partials (alias into A region; all LDSM of both groups done) ----
        __syncthreads();
#pragma unroll
        for (int gate = 0; gate < 4; gate++) {
            int col = gate * 8 + 2 * ztg;
            *(float2*)&z_s[((kg * 64) + wm + zg) * 34 + col] =
                make_float2(acc[gate][0], acc[gate][1]);
            *(float2*)&z_s[((kg * 64) + wm + zg + 8) * 34 + col] =
                make_float2(acc[gate][2], acc[gate][3]);
        }
        __syncthreads();

        // ---- pointwise LSTM update (fast sigmoid/tanh: MUFU only) ----
        {
            int b = pb, hl = phl;
            float zi = rzx[0], zj = rzx[1], zf = rzx[2], zo = rzx[3];
#pragma unroll
            for (int g2 = 0; g2 < 4; g2++) {
                const float* zp = &z_s[(g2 * 64 + b) * 34];
                zi += zp[0 + hl];
                zj += zp[8 + hl];
                zf += zp[16 + hl];
                zo += zp[24 + hl];
            }

            float ig = fsig(zi);
            float jg = ftanh(zj);
            float fg = fsig(zf + 1.f);
            float og = fsig(zo);

            float cnew = fg * c_reg + ig * jg;
            float hnew = og * ftanh(cnew);
            c_reg = cnew;

            __nv_bfloat16 hhi = __float2bfloat16(hnew);
            __nv_bfloat16 hlo = __float2bfloat16(hnew - __bfloat162float(hhi));
            g_hb[dir][buf ^ 1][0][b][h0 + hl] = hhi;
            g_hb[dir][buf ^ 1][1][b][h0 + hl] = hlo;
            out[((size_t)b * TT + tin) * (2 * HH) + dir * HH + h0 + hl] = hnew;
        }

        grid_barrier(dir, (unsigned)(t + 1));
    }
}

extern "C" void kernel_launch(void* const* d_in, const int* in_sizes, int n_in,
                              void* d_out, int out_size) {
    const float* x   = (const float*)d_in[0];
    const float* Wfw = (const float*)d_in[1];
    const float* bfw = (const float*)d_in[2];
    const float* Wbw = (const float*)d_in[3];
    const float* bbw = (const float*)d_in[4];
    float* out = (float*)d_out;

    static int attr_done = 0;
    if (!attr_done) {
        cudaFuncSetAttribute(lstm_persist, cudaFuncAttributeMaxDynamicSharedMemorySize,
                             PERSIST_SMEM);
        cudaFuncSetAttribute(pregemm_mma, cudaFuncAttributeMaxDynamicSharedMemorySize,
                             PG_SMEM);
        attr_done = 1;
    }

    prep_ab<<<(TT * BB * DD) / 256, 256>>>(x);
    prep_w<<<(4 * G4H * DD + 255) / 256, 256>>>(Wfw, Wbw);

    pregemm_mma<<<dim3(G4H / 128, (TT * BB) / 128, 2), 256, PG_SMEM>>>(bfw, bbw);

    lstm_persist<<<dim3(64, 2), 512, PERSIST_SMEM>>>(out);
}

// round 14
// speedup vs baseline: 1.7611x; 1.0337x over previous
#include <cuda_runtime.h>
#include <cuda_bf16.h>
#include <stdint.h>
#include <math.h>

#define BB 64
#define TT 512
#define DD 512
#define HH 512
#define G4H 2048  // 4*H

typedef unsigned long long ull;
typedef unsigned int u32;

// -------- device scratch (no cudaMalloc allowed) --------
__device__ float g_Zx[2][TT * BB][G4H];          // x-projection + bias
__device__ volatile unsigned g_phase[2];
__device__ unsigned g_arrive[2];
__device__ __nv_bfloat16 g_Ahi[TT * BB][DD];     // x reordered (m=t*B+b), bf16 hi
__device__ __nv_bfloat16 g_Alo[TT * BB][DD];     // bf16 lo
__device__ __nv_bfloat16 g_WT[2][2][G4H][DD];    // W[:512] transposed [dir][hi/lo][n][k]
__device__ __nv_bfloat16 g_WhT[2][2][G4H][DD];   // W[512:] transposed [dir][hi/lo][n][k]
__device__ __nv_bfloat16 g_hb[2][2][2][BB][HH];  // h state [dir][buf][hi/lo][b][k]

// ---- helpers ----
#define CP_ASYNC16(smem_addr, gptr) \
    asm volatile("cp.async.cg.shared.global [%0], [%1], 16;" :: "r"(smem_addr), "l"(gptr))
#define CP_COMMIT()  asm volatile("cp.async.commit_group;")
#define CP_WAIT0()   asm volatile("cp.async.wait_group 0;" ::: "memory")
#define CP_WAIT1()   asm volatile("cp.async.wait_group 1;" ::: "memory")

// fast sigmoid/tanh: MUFU.EX2 + MUFU.RCP only (NaN-safe at +-inf of exp)
__device__ __forceinline__ float fsig(float x)  { return __fdividef(1.f, 1.f + __expf(-x)); }
__device__ __forceinline__ float ftanh(float x) { return __fdividef(2.f, 1.f + __expf(-2.f * x)) - 1.f; }

__device__ __forceinline__ void mma16816(float* c, const u32* a, u32 b0, u32 b1) {
    asm volatile(
        "mma.sync.aligned.m16n8k16.row.col.f32.bf16.bf16.f32 "
        "{%0,%1,%2,%3}, {%4,%5,%6,%7}, {%8,%9}, {%0,%1,%2,%3};"
        : "+f"(c[0]), "+f"(c[1]), "+f"(c[2]), "+f"(c[3])
        : "r"(a[0]), "r"(a[1]), "r"(a[2]), "r"(a[3]), "r"(b0), "r"(b1));
}

#define LDSM_X4(r0, r1, r2, r3, addr) \
    asm volatile("ldmatrix.sync.aligned.m8n8.x4.shared.b16 {%0,%1,%2,%3}, [%4];" \
                 : "=r"(r0), "=r"(r1), "=r"(r2), "=r"(r3) : "r"(addr))

__device__ __forceinline__ u32 smem_u32(const void* p) {
    u32 a;
    asm("{ .reg .u64 t; cvta.to.shared.u64 t, %1; cvt.u32.u64 %0, t; }" : "=r"(a) : "l"(p));
    return a;
}

// -------- prep: split x into bf16 hi/lo (m = t*B + b); init h/barrier state --------
__global__ void prep_ab(const float* __restrict__ x) {
    int idx = blockIdx.x * blockDim.x + threadIdx.x;
    int d = idx & 511;
    int m = idx >> 9;
    int t = m >> 6, b = m & 63;
    float v = x[((size_t)b * TT + t) * DD + d];
    __nv_bfloat16 hi = __float2bfloat16(v);
    float lo = v - __bfloat162float(hi);
    g_Ahi[m][d] = hi;
    g_Alo[m][d] = __float2bfloat16(lo);
    if (idx < 2 * 2 * 2 * BB * HH)
        (&g_hb[0][0][0][0][0])[idx] = __float2bfloat16(0.f);
    if (idx == 0) { g_phase[0] = 0; g_phase[1] = 0; g_arrive[0] = 0; g_arrive[1] = 0; }
}

// -------- prep: tiled transpose + bf16 hi/lo split of W (both halves) --------
// grid 4096 blocks x 256 thr; block handles one 32(k) x 32(n) tile.
__global__ void prep_w(const float* __restrict__ Wfw, const float* __restrict__ Wbw) {
    __shared__ float ts[32][33];
    int bid = blockIdx.x;
    int nt   = bid & 63;          // n-tile 0..63
    int kt   = (bid >> 6) & 15;   // k-tile 0..15
    int half = (bid >> 10) & 1;   // 0: W[:512], 1: W[512:]
    int dir  = bid >> 11;
    const float* Wm = dir ? Wbw : Wfw;

    int tx = threadIdx.x & 31;
    int ty = threadIdx.x >> 5;    // 0..7

    // coalesced read: threads sweep n
#pragma unroll
    for (int i = ty; i < 32; i += 8)
        ts[i][tx] = Wm[(size_t)(half * 512 + kt * 32 + i) * G4H + nt * 32 + tx];
    __syncthreads();

    __nv_bfloat16* dhi = half ? &g_WhT[dir][0][0][0] : &g_WT[dir][0][0][0];
    __nv_bfloat16* dlo = half ? &g_WhT[dir][1][0][0] : &g_WT[dir][1][0][0];

    // coalesced write: threads sweep k; smem read ts[tx][i] is conflict-free (pad 33)
#pragma unroll
    for (int i = ty; i < 32; i += 8) {
        float v = ts[tx][i];
        __nv_bfloat16 hi = __float2bfloat16(v);
        size_t o = (size_t)(nt * 32 + i) * DD + kt * 32 + tx;
        dhi[o] = hi;
        dlo[o] = __float2bfloat16(v - __bfloat162float(hi));
    }
}

// -------- mma.sync + ldmatrix x-projection GEMM (unchanged, verified) --------
#define PK      40
#define TILE_B  (128 * PK * 2)
#define PG_SMEM (8 * TILE_B)

__global__ void __launch_bounds__(256, 2)
pregemm_mma(const float* __restrict__ bfw, const float* __restrict__ bbw) {
    extern __shared__ char smc[];
    u32 smb = smem_u32(smc);
    int dir = blockIdx.z;
    int n0 = blockIdx.x * 128;
    int m0 = blockIdx.y * 128;
    const float* bias = dir ? bbw : bfw;

    int tid  = threadIdx.x;
    int warp = tid >> 5;
    int lane = tid & 31;
    int g  = lane >> 2;
    int tg = lane & 3;

    int wm = (warp & 3) * 32;
    int wn = (warp >> 2) * 64;

    int lrow  = tid >> 2;
    int lkcol = (tid & 3) * 8;
    const __nv_bfloat16* gsrc[4];
    gsrc[0] = &g_Ahi[m0][0];
    gsrc[1] = &g_Alo[m0][0];
    gsrc[2] = &g_WT[dir][0][n0][0];
    gsrc[3] = &g_WT[dir][1][n0][0];

    int rowA  = lane & 15;
    int koffA = (lane >> 4) * 8;
    int rowB  = (lane & 7) + ((lane >> 4) << 3);
    int koffB = ((lane >> 3) & 1) * 8;
    u32 aoff = (u32)(((wm + rowA) * PK + koffA) * 2);
    u32 boff = (u32)(((wn + rowB) * PK + koffB) * 2);

    float acc[2][8][4];
#pragma unroll
    for (int i = 0; i < 2; i++)
#pragma unroll
        for (int j = 0; j < 8; j++)
#pragma unroll
            for (int q = 0; q < 4; q++) acc[i][j][q] = 0.f;

    auto load_chunk = [&](int c, int buf) {
#pragma unroll
        for (int tile = 0; tile < 4; tile++) {
            u32 base = smb + (tile < 2 ? 0 : 4 * TILE_B) + (buf * 2 + (tile & 1)) * TILE_B;
#pragma unroll
            for (int it = 0; it < 2; it++) {
                int row = lrow + it * 64;
                const __nv_bfloat16* src = gsrc[tile] + (size_t)row * DD + c * 32 + lkcol;
                u32 dst = base + (u32)((row * PK + lkcol) * 2);
                CP_ASYNC16(dst, src);
            }
        }
        CP_COMMIT();
    };

    load_chunk(0, 0);

#pragma unroll 1
    for (int c = 0; c < 16; ++c) {
        int buf = c & 1;
        if (c < 15) { load_chunk(c + 1, buf ^ 1); CP_WAIT1(); }
        else        { CP_WAIT0(); }
        __syncthreads();

        u32 aBase0 = smb + (buf * 2 + 0) * TILE_B + aoff;
        u32 aBase1 = smb + (buf * 2 + 1) * TILE_B + aoff;
        u32 bBase0 = smb + 4 * TILE_B + (buf * 2 + 0) * TILE_B + boff;
        u32 bBase1 = smb + 4 * TILE_B + (buf * 2 + 1) * TILE_B + boff;

#pragma unroll
        for (int k16 = 0; k16 < 2; ++k16) {
            u32 kb = (u32)(k16 * 32);
            u32 ah[2][4], al[2][4];
#pragma unroll
            for (int mt = 0; mt < 2; mt++) {
                LDSM_X4(ah[mt][0], ah[mt][1], ah[mt][2], ah[mt][3],
                        aBase0 + kb + mt * (16 * PK * 2));
                LDSM_X4(al[mt][0], al[mt][1], al[mt][2], al[mt][3],
                        aBase1 + kb + mt * (16 * PK * 2));
            }
#pragma unroll
            for (int ng = 0; ng < 4; ng++) {
                u32 bh[4], bl[4];
                LDSM_X4(bh[0], bh[1], bh[2], bh[3], bBase0 + kb + ng * (16 * PK * 2));
                LDSM_X4(bl[0], bl[1], bl[2], bl[3], bBase1 + kb + ng * (16 * PK * 2));
#pragma unroll
                for (int mt = 0; mt < 2; mt++) {
                    mma16816(acc[mt][ng * 2],     ah[mt], bh[0], bh[1]);
                    mma16816(acc[mt][ng * 2 + 1], ah[mt], bh[2], bh[3]);
                    mma16816(acc[mt][ng * 2],     ah[mt], bl[0], bl[1]);
                    mma16816(acc[mt][ng * 2 + 1], ah[mt], bl[2], bl[3]);
                    mma16816(acc[mt][ng * 2],     al[mt], bh[0], bh[1]);
                    mma16816(acc[mt][ng * 2 + 1], al[mt], bh[2], bh[3]);
                }
            }
        }
        __syncthreads();
    }

#pragma unroll
    for (int nt = 0; nt < 8; nt++) {
        int col = n0 + wn + nt * 8 + 2 * tg;
        float b0 = bias[col], b1 = bias[col + 1];
#pragma unroll
        for (int mt = 0; mt < 2; mt++) {
            int row0 = m0 + wm + mt * 16 + g;
            float2 v0 = make_float2(acc[mt][nt][0] + b0, acc[mt][nt][1] + b1);
            float2 v1 = make_float2(acc[mt][nt][2] + b0, acc[mt][nt][3] + b1);
            *(float2*)&g_Zx[dir][row0][col]     = v0;
            *(float2*)&g_Zx[dir][row0 + 8][col] = v1;
        }
    }
}

// -------- per-direction grid barrier --------
__device__ __forceinline__ void grid_barrier(int dir, unsigned target) {
    __syncthreads();
    if (threadIdx.x == 0) {
        __threadfence();
        unsigned old = atomicAdd(&g_arrive[dir], 1);
        if (old == 63) {
            g_arrive[dir] = 0;
            __threadfence();
            g_phase[dir] = target;
        } else {
            while (g_phase[dir] < target) { }
            __threadfence();
        }
    }
    __syncthreads();
}

// -------- persistent recurrent kernel: bf16-split mma.sync, per-kg staging --------
#define PKH       520
#define A_SPLIT_B (64 * PKH * 2)      // 66560
#define B_SPLIT_B (32 * PKH * 2)      // 33280
#define OFF_ALO   A_SPLIT_B
#define OFF_BHI   (2 * A_SPLIT_B)
#define OFF_BLO   (2 * A_SPLIT_B + B_SPLIT_B)
#define PERSIST_SMEM (2 * A_SPLIT_B + 2 * B_SPLIT_B)   // 199680

__global__ void __launch_bounds__(512, 1)
lstm_persist(float* __restrict__ out) {
    extern __shared__ char smc[];
    u32 smb = smem_u32(smc);
    float* z_s = (float*)smc;                 // [4][64][34] alias of A region

    int dir = blockIdx.y;
    int hb  = blockIdx.x;
    int h0  = hb * 8;

    int tid  = threadIdx.x;
    int warp = tid >> 5;
    int lane = tid & 31;
    int mt = warp & 3;          // m-tile: batch rows mt*16..
    int kg = warp >> 2;         // k-split: k in [kg*128, kg*128+128)
    int wm = mt * 16;
    int kgt = tid & 127;        // thread within kg group (4 warps)

    // ---- load resident B slice (32 gathered n-rows x 512 k x 2 splits) ----
    for (int c = tid; c < 4096; c += 512) {
        int split = c >> 11;
        int r  = (c & 2047) >> 6;
        int ch = c & 63;
        int gate = r >> 3, hl = r & 7;
        const __nv_bfloat16* src = &g_WhT[dir][split][gate * 512 + h0 + hl][ch * 8];
        u32 dst = smb + OFF_BHI + split * B_SPLIT_B + (u32)(r * PKH * 2 + ch * 16);
        CP_ASYNC16(dst, src);
    }
    CP_COMMIT();

    // fragment offsets (mappings verified)
    int rowA  = lane & 15;
    int koffA = (lane >> 4) * 8;
    int rowB  = (lane & 7) + ((lane >> 4) << 3);
    int koffB = ((lane >> 3) & 1) * 8;
    u32 aoff = (u32)(((wm + rowA) * PKH + koffA) * 2);
    u32 boff = (u32)((rowB * PKH + koffB) * 2);

    int pb = tid >> 3, phl = tid & 7;   // pointwise: 1 (b,h) per thread
    float c_reg = 0.f;

    int zg = lane >> 2;
    int ztg = lane & 3;

    CP_WAIT0();
    __syncthreads();

#pragma unroll 1
    for (int t = 0; t < TT; ++t) {
        int tin = dir ? (TT - 1 - t) : t;
        int buf = t & 1;

        // ---- each kg group stages only its own k-quarter of h hi/lo ----
        {
            const __nv_bfloat16* hg = &g_hb[dir][buf][0][0][0];
#pragma unroll
            for (int j = 0; j < 16; ++j) {
                int c = kgt + j * 128;           // 0..2047 within group's quarter
                int split = c >> 10;
                int rem = c & 1023;
                int r  = rem >> 4;               // 0..63 (batch)
                int ch = rem & 15;               // 16B chunk within k-quarter
                u32 dst = smb + split * A_SPLIT_B +
                          (u32)(r * (PKH * 2) + (kg * 128 + ch * 8) * 2);
                CP_ASYNC16(dst, hg + (size_t)split * BB * HH + r * 512 + kg * 128 + ch * 8);
            }
            CP_COMMIT();
        }

        // prefetch Zx for this step (hidden behind staging wait)
        float rzx[4];
        {
            const float* zp = &g_Zx[dir][tin * BB + pb][h0 + phl];
#pragma unroll
            for (int g = 0; g < 4; g++) rzx[g] = zp[g * 512];
        }

        CP_WAIT0();
        asm volatile("bar.sync %0, 128;" :: "r"(1 + kg) : "memory");

        float acc[4][4];
#pragma unroll
        for (int i = 0; i < 4; i++)
#pragma unroll
            for (int q = 0; q < 4; q++) acc[i][q] = 0.f;

        u32 aBaseH = smb + aoff;
        u32 aBaseL = smb + OFF_ALO + aoff;
        u32 bBaseH = smb + OFF_BHI + boff;
        u32 bBaseL = smb + OFF_BLO + boff;
        int kbase = kg * 128;

#pragma unroll
        for (int k16 = 0; k16 < 8; ++k16) {
            u32 kb = (u32)((kbase + k16 * 16) * 2);
            u32 ah[4], al[4];
            LDSM_X4(ah[0], ah[1], ah[2], ah[3], aBaseH + kb);
            LDSM_X4(al[0], al[1], al[2], al[3], aBaseL + kb);
#pragma unroll
            for (int g2 = 0; g2 < 2; ++g2) {
                u32 gofs = (u32)(g2 * 16 * PKH * 2);
                u32 bh[4], bl[4];
                LDSM_X4(bh[0], bh[1], bh[2], bh[3], bBaseH + kb + gofs);
                LDSM_X4(bl[0], bl[1], bl[2], bl[3], bBaseL + kb + gofs);
                mma16816(acc[g2 * 2],     ah, bh[0], bh[1]);
                mma16816(acc[g2 * 2 + 1], ah, bh[2], bh[3]);
                mma16816(acc[g2 * 2],     ah, bl[0], bl[1]);
                mma16816(acc[g2 * 2 + 1], ah, bl[2], bl[3]);
                mma16816(acc[g2 * 2],     al, bh[0], bh[1]);
                mma16816(acc[g2 * 2 + 1], al, bh[2], bh[3]);
            }
        }

        // ---- stash z partials (alias into A region; all groups' LDSM done) ----
        __syncthreads();
#pragma unroll
        for (int gate = 0; gate < 4; gate++) {
            int col = gate * 8 + 2 * ztg;
            *(float2*)&z_s[((kg * 64) + wm + zg) * 34 + col] =
                make_float2(acc[gate][0], acc[gate][1]);
            *(float2*)&z_s[((kg * 64) + wm + zg + 8) * 34 + col] =
                make_float2(acc[gate][2], acc[gate][3]);
        }
        __syncthreads();

        // ---- pointwise LSTM update (MUFU-only activations) ----
        {
            int b = pb, hl = phl;
            float zi = rzx[0], zj = rzx[1], zf = rzx[2], zo = rzx[3];
#pragma unroll
            for (int g2 = 0; g2 < 4; g2++) {
                const float* zp = &z_s[(g2 * 64 + b) * 34];
                zi += zp[0 + hl];
                zj += zp[8 + hl];
                zf += zp[16 + hl];
                zo += zp[24 + hl];
            }

            float ig = fsig(zi);
            float jg = ftanh(zj);
            float fg = fsig(zf + 1.f);
            float og = fsig(zo);

            float cnew = fg * c_reg + ig * jg;
            float hnew = og * ftanh(cnew);
            c_reg = cnew;

            __nv_bfloat16 hhi = __float2bfloat16(hnew);
            __nv_bfloat16 hlo = __float2bfloat16(hnew - __bfloat162float(hhi));
            g_hb[dir][buf ^ 1][0][b][h0 + hl] = hhi;
            g_hb[dir][buf ^ 1][1][b][h0 + hl] = hlo;
            out[((size_t)b * TT + tin) * (2 * HH) + dir * HH + h0 + hl] = hnew;
        }

        grid_barrier(dir, (unsigned)(t + 1));
    }
}

extern "C" void kernel_launch(void* const* d_in, const int* in_sizes, int n_in,
                              void* d_out, int out_size) {
    const float* x   = (const float*)d_in[0];
    const float* Wfw = (const float*)d_in[1];
    const float* bfw = (const float*)d_in[2];
    const float* Wbw = (const float*)d_in[3];
    const float* bbw = (const float*)d_in[4];
    float* out = (float*)d_out;

    static int attr_done = 0;
    if (!attr_done) {
        cudaFuncSetAttribute(lstm_persist, cudaFuncAttributeMaxDynamicSharedMemorySize,
                             PERSIST_SMEM);
        cudaFuncSetAttribute(pregemm_mma, cudaFuncAttributeMaxDynamicSharedMemorySize,
                             PG_SMEM);
        attr_done = 1;
    }

    prep_ab<<<(TT * BB * DD) / 256, 256>>>(x);
    prep_w<<<4096, 256>>>(Wfw, Wbw);

    pregemm_mma<<<dim3(G4H / 128, (TT * BB) / 128, 2), 256, PG_SMEM>>>(bfw, bbw);

    lstm_persist<<<dim3(64, 2), 512, PERSIST_SMEM>>>(out);
}

// round 15
// speedup vs baseline: 2.1249x; 1.2066x over previous
#include <cuda_runtime.h>
#include <cuda_bf16.h>
#include <stdint.h>
#include <math.h>

#define BB 64
#define TT 512
#define DD 512
#define HH 512
#define G4H 2048  // 4*H

typedef unsigned long long ull;
typedef unsigned int u32;

// -------- device scratch (no cudaMalloc allowed) --------
__device__ float g_Zx[2][TT * BB][G4H];          // x-projection + bias
__device__ volatile unsigned g_phase[2];
__device__ unsigned g_arrive[2];
__device__ __nv_bfloat16 g_Ahi[TT * BB][DD];     // x reordered (m=t*B+b), bf16 hi
__device__ __nv_bfloat16 g_Alo[TT * BB][DD];     // bf16 lo
__device__ __nv_bfloat16 g_WT[2][2][G4H][DD];    // W[:512] transposed [dir][hi/lo][n][k]
__device__ __nv_bfloat16 g_WhT[2][2][G4H][DD];   // W[512:] transposed [dir][hi/lo][n][k]
// h state in MMA A-fragment layout: [dir][buf][split][k16 tile][mtile][lane][reg]
__device__ u32 g_hfrag[2][2][2][32 * 4 * 32 * 4];

// ---- helpers ----
#define CP_ASYNC16(smem_addr, gptr) \
    asm volatile("cp.async.cg.shared.global [%0], [%1], 16;" :: "r"(smem_addr), "l"(gptr))
#define CP_COMMIT()  asm volatile("cp.async.commit_group;")
#define CP_WAIT0()   asm volatile("cp.async.wait_group 0;" ::: "memory")
#define CP_WAIT1()   asm volatile("cp.async.wait_group 1;" ::: "memory")

// fast sigmoid/tanh: MUFU.EX2 + MUFU.RCP only (NaN-safe at +-inf of exp)
__device__ __forceinline__ float fsig(float x)  { return __fdividef(1.f, 1.f + __expf(-x)); }
__device__ __forceinline__ float ftanh(float x) { return __fdividef(2.f, 1.f + __expf(-2.f * x)) - 1.f; }

__device__ __forceinline__ void mma16816(float* c, const u32* a, u32 b0, u32 b1) {
    asm volatile(
        "mma.sync.aligned.m16n8k16.row.col.f32.bf16.bf16.f32 "
        "{%0,%1,%2,%3}, {%4,%5,%6,%7}, {%8,%9}, {%0,%1,%2,%3};"
        : "+f"(c[0]), "+f"(c[1]), "+f"(c[2]), "+f"(c[3])
        : "r"(a[0]), "r"(a[1]), "r"(a[2]), "r"(a[3]), "r"(b0), "r"(b1));
}

#define LDSM_X4(r0, r1, r2, r3, addr) \
    asm volatile("ldmatrix.sync.aligned.m8n8.x4.shared.b16 {%0,%1,%2,%3}, [%4];" \
                 : "=r"(r0), "=r"(r1), "=r"(r2), "=r"(r3) : "r"(addr))

__device__ __forceinline__ u32 smem_u32(const void* p) {
    u32 a;
    asm("{ .reg .u64 t; cvta.to.shared.u64 t, %1; cvt.u32.u64 %0, t; }" : "=r"(a) : "l"(p));
    return a;
}

// -------- prep: split x into bf16 hi/lo (m = t*B + b); init h/barrier state --------
__global__ void prep_ab(const float* __restrict__ x) {
    int idx = blockIdx.x * blockDim.x + threadIdx.x;
    int d = idx & 511;
    int m = idx >> 9;
    int t = m >> 6, b = m & 63;
    float v = x[((size_t)b * TT + t) * DD + d];
    __nv_bfloat16 hi = __float2bfloat16(v);
    float lo = v - __bfloat162float(hi);
    g_Ahi[m][d] = hi;
    g_Alo[m][d] = __float2bfloat16(lo);
    if (idx < 2 * 2 * 2 * 32 * 4 * 32 * 4)
        (&g_hfrag[0][0][0][0])[idx] = 0u;
    if (idx == 0) { g_phase[0] = 0; g_phase[1] = 0; g_arrive[0] = 0; g_arrive[1] = 0; }
}

// -------- prep: tiled transpose + bf16 hi/lo split of W (both halves) --------
__global__ void prep_w(const float* __restrict__ Wfw, const float* __restrict__ Wbw) {
    __shared__ float ts[32][33];
    int bid = blockIdx.x;
    int nt   = bid & 63;
    int kt   = (bid >> 6) & 15;
    int half = (bid >> 10) & 1;
    int dir  = bid >> 11;
    const float* Wm = dir ? Wbw : Wfw;

    int tx = threadIdx.x & 31;
    int ty = threadIdx.x >> 5;

#pragma unroll
    for (int i = ty; i < 32; i += 8)
        ts[i][tx] = Wm[(size_t)(half * 512 + kt * 32 + i) * G4H + nt * 32 + tx];
    __syncthreads();

    __nv_bfloat16* dhi = half ? &g_WhT[dir][0][0][0] : &g_WT[dir][0][0][0];
    __nv_bfloat16* dlo = half ? &g_WhT[dir][1][0][0] : &g_WT[dir][1][0][0];

#pragma unroll
    for (int i = ty; i < 32; i += 8) {
        float v = ts[tx][i];
        __nv_bfloat16 hi = __float2bfloat16(v);
        size_t o = (size_t)(nt * 32 + i) * DD + kt * 32 + tx;
        dhi[o] = hi;
        dlo[o] = __float2bfloat16(v - __bfloat162float(hi));
    }
}

// -------- mma.sync + ldmatrix x-projection GEMM (unchanged, verified) --------
#define PK      40
#define TILE_B  (128 * PK * 2)
#define PG_SMEM (8 * TILE_B)

__global__ void __launch_bounds__(256, 2)
pregemm_mma(const float* __restrict__ bfw, const float* __restrict__ bbw) {
    extern __shared__ char smc[];
    u32 smb = smem_u32(smc);
    int dir = blockIdx.z;
    int n0 = blockIdx.x * 128;
    int m0 = blockIdx.y * 128;
    const float* bias = dir ? bbw : bfw;

    int tid  = threadIdx.x;
    int warp = tid >> 5;
    int lane = tid & 31;
    int g  = lane >> 2;
    int tg = lane & 3;

    int wm = (warp & 3) * 32;
    int wn = (warp >> 2) * 64;

    int lrow  = tid >> 2;
    int lkcol = (tid & 3) * 8;
    const __nv_bfloat16* gsrc[4];
    gsrc[0] = &g_Ahi[m0][0];
    gsrc[1] = &g_Alo[m0][0];
    gsrc[2] = &g_WT[dir][0][n0][0];
    gsrc[3] = &g_WT[dir][1][n0][0];

    int rowA  = lane & 15;
    int koffA = (lane >> 4) * 8;
    int rowB  = (lane & 7) + ((lane >> 4) << 3);
    int koffB = ((lane >> 3) & 1) * 8;
    u32 aoff = (u32)(((wm + rowA) * PK + koffA) * 2);
    u32 boff = (u32)(((wn + rowB) * PK + koffB) * 2);

    float acc[2][8][4];
#pragma unroll
    for (int i = 0; i < 2; i++)
#pragma unroll
        for (int j = 0; j < 8; j++)
#pragma unroll
            for (int q = 0; q < 4; q++) acc[i][j][q] = 0.f;

    auto load_chunk = [&](int c, int buf) {
#pragma unroll
        for (int tile = 0; tile < 4; tile++) {
            u32 base = smb + (tile < 2 ? 0 : 4 * TILE_B) + (buf * 2 + (tile & 1)) * TILE_B;
#pragma unroll
            for (int it = 0; it < 2; it++) {
                int row = lrow + it * 64;
                const __nv_bfloat16* src = gsrc[tile] + (size_t)row * DD + c * 32 + lkcol;
                u32 dst = base + (u32)((row * PK + lkcol) * 2);
                CP_ASYNC16(dst, src);
            }
        }
        CP_COMMIT();
    };

    load_chunk(0, 0);

#pragma unroll 1
    for (int c = 0; c < 16; ++c) {
        int buf = c & 1;
        if (c < 15) { load_chunk(c + 1, buf ^ 1); CP_WAIT1(); }
        else        { CP_WAIT0(); }
        __syncthreads();

        u32 aBase0 = smb + (buf * 2 + 0) * TILE_B + aoff;
        u32 aBase1 = smb + (buf * 2 + 1) * TILE_B + aoff;
        u32 bBase0 = smb + 4 * TILE_B + (buf * 2 + 0) * TILE_B + boff;
        u32 bBase1 = smb + 4 * TILE_B + (buf * 2 + 1) * TILE_B + boff;

#pragma unroll
        for (int k16 = 0; k16 < 2; ++k16) {
            u32 kb = (u32)(k16 * 32);
            u32 ah[2][4], al[2][4];
#pragma unroll
            for (int mt = 0; mt < 2; mt++) {
                LDSM_X4(ah[mt][0], ah[mt][1], ah[mt][2], ah[mt][3],
                        aBase0 + kb + mt * (16 * PK * 2));
                LDSM_X4(al[mt][0], al[mt][1], al[mt][2], al[mt][3],
                        aBase1 + kb + mt * (16 * PK * 2));
            }
#pragma unroll
            for (int ng = 0; ng < 4; ng++) {
                u32 bh[4], bl[4];
                LDSM_X4(bh[0], bh[1], bh[2], bh[3], bBase0 + kb + ng * (16 * PK * 2));
                LDSM_X4(bl[0], bl[1], bl[2], bl[3], bBase1 + kb + ng * (16 * PK * 2));
#pragma unroll
                for (int mt = 0; mt < 2; mt++) {
                    mma16816(acc[mt][ng * 2],     ah[mt], bh[0], bh[1]);
                    mma16816(acc[mt][ng * 2 + 1], ah[mt], bh[2], bh[3]);
                    mma16816(acc[mt][ng * 2],     ah[mt], bl[0], bl[1]);
                    mma16816(acc[mt][ng * 2 + 1], ah[mt], bl[2], bl[3]);
                    mma16816(acc[mt][ng * 2],     al[mt], bh[0], bh[1]);
                    mma16816(acc[mt][ng * 2 + 1], al[mt], bh[2], bh[3]);
                }
            }
        }
        __syncthreads();
    }

#pragma unroll
    for (int nt = 0; nt < 8; nt++) {
        int col = n0 + wn + nt * 8 + 2 * tg;
        float b0 = bias[col], b1 = bias[col + 1];
#pragma unroll
        for (int mt = 0; mt < 2; mt++) {
            int row0 = m0 + wm + mt * 16 + g;
            float2 v0 = make_float2(acc[mt][nt][0] + b0, acc[mt][nt][1] + b1);
            float2 v1 = make_float2(acc[mt][nt][2] + b0, acc[mt][nt][3] + b1);
            *(float2*)&g_Zx[dir][row0][col]     = v0;
            *(float2*)&g_Zx[dir][row0 + 8][col] = v1;
        }
    }
}

// -------- per-direction grid barrier --------
__device__ __forceinline__ void grid_barrier(int dir, unsigned target) {
    __syncthreads();
    if (threadIdx.x == 0) {
        __threadfence();
        unsigned old = atomicAdd(&g_arrive[dir], 1);
        if (old == 63) {
            g_arrive[dir] = 0;
            __threadfence();
            g_phase[dir] = target;
        } else {
            while (g_phase[dir] < target) { }
            __threadfence();
        }
    }
    __syncthreads();
}

// -------- persistent recurrent kernel: h in fragment layout, zero staging --------
#define PKH       520
#define B_SPLIT_B (32 * PKH * 2)            // 33280
#define Z_BYTES   (4 * 64 * 34 * 4)         // 34816
#define PERSIST_SMEM (Z_BYTES + 2 * B_SPLIT_B)   // 101376

__global__ void __launch_bounds__(512, 1)
lstm_persist(float* __restrict__ out) {
    extern __shared__ char smc[];
    u32 smb = smem_u32(smc);
    float* z_s = (float*)smc;                 // [4][64][34]

    int dir = blockIdx.y;
    int hb  = blockIdx.x;
    int h0  = hb * 8;

    int tid  = threadIdx.x;
    int warp = tid >> 5;
    int lane = tid & 31;
    int mt = warp & 3;          // m-tile: batch rows mt*16..
    int kg = warp >> 2;         // k-split: k in [kg*128, kg*128+128)

    // ---- load resident B slice (32 gathered n-rows x 512 k x 2 splits) ----
    for (int c = tid; c < 4096; c += 512) {
        int split = c >> 11;
        int r  = (c & 2047) >> 6;
        int ch = c & 63;
        int gate = r >> 3, hl = r & 7;
        const __nv_bfloat16* src = &g_WhT[dir][split][gate * 512 + h0 + hl][ch * 8];
        u32 dst = smb + Z_BYTES + split * B_SPLIT_B + (u32)(r * PKH * 2 + ch * 16);
        CP_ASYNC16(dst, src);
    }
    CP_COMMIT();

    // B fragment offsets (verified mapping)
    int rowB  = (lane & 7) + ((lane >> 4) << 3);
    int koffB = ((lane >> 3) & 1) * 8;
    u32 boff = (u32)((rowB * PKH + koffB) * 2);

    int pb = tid >> 3, phl = tid & 7;   // pointwise: 1 (b,h) per thread
    float c_reg = 0.f;

    // writer constants for fragment store
    int w_reg  = ((hb & 1) << 1) | ((pb >> 3) & 1);
    int w_lane = ((pb & 7) << 2) | (phl >> 1);
    int w_mt   = pb >> 4;
    size_t w_off = (((size_t)(hb >> 1) * 4 + w_mt) * 32 + w_lane) * 4 + w_reg;

    int zg = lane >> 2;
    int ztg = lane & 3;

    CP_WAIT0();
    __syncthreads();

#pragma unroll 1
    for (int t = 0; t < TT; ++t) {
        int tin = dir ? (TT - 1 - t) : t;
        int buf = t & 1;

        const u32* fr0 = &g_hfrag[dir][buf][0][0];
        const u32* fr1 = &g_hfrag[dir][buf][1][0];

        // prefetch Zx for this step
        float rzx[4];
        {
            const float* zp = &g_Zx[dir][tin * BB + pb][h0 + phl];
#pragma unroll
            for (int g = 0; g < 4; g++) rzx[g] = zp[g * 512];
        }

        float acc[4][4];
#pragma unroll
        for (int i = 0; i < 4; i++)
#pragma unroll
            for (int q = 0; q < 4; q++) acc[i][q] = 0.f;

        u32 bBaseH = smb + Z_BYTES + boff;
        u32 bBaseL = smb + Z_BYTES + B_SPLIT_B + boff;

        // ---- A fragments via direct coalesced LDG.128; B via resident ldmatrix ----
#pragma unroll
        for (int jj = 0; jj < 2; ++jj) {
            uint4 fh[4], fl[4];
#pragma unroll
            for (int j = 0; j < 4; j++) {
                int tt = kg * 8 + jj * 4 + j;
                size_t o = (((size_t)tt * 4 + mt) * 32 + lane) * 4;
                fh[j] = *(const uint4*)(fr0 + o);
                fl[j] = *(const uint4*)(fr1 + o);
            }
#pragma unroll
            for (int j = 0; j < 4; j++) {
                u32 kb = (u32)((kg * 128 + (jj * 4 + j) * 16) * 2);
#pragma unroll
                for (int g2 = 0; g2 < 2; ++g2) {
                    u32 gofs = (u32)(g2 * 16 * PKH * 2);
                    u32 bh[4], bl[4];
                    LDSM_X4(bh[0], bh[1], bh[2], bh[3], bBaseH + kb + gofs);
                    LDSM_X4(bl[0], bl[1], bl[2], bl[3], bBaseL + kb + gofs);
                    const u32* ah = (const u32*)&fh[j];
                    const u32* al = (const u32*)&fl[j];
                    mma16816(acc[g2 * 2],     ah, bh[0], bh[1]);
                    mma16816(acc[g2 * 2 + 1], ah, bh[2], bh[3]);
                    mma16816(acc[g2 * 2],     ah, bl[0], bl[1]);
                    mma16816(acc[g2 * 2 + 1], ah, bl[2], bl[3]);
                    mma16816(acc[g2 * 2],     al, bh[0], bh[1]);
                    mma16816(acc[g2 * 2 + 1], al, bh[2], bh[3]);
                }
            }
        }

        // ---- stash z partials (no pre-sync needed: readers passed grid barrier) ----
#pragma unroll
        for (int gate = 0; gate < 4; gate++) {
            int col = gate * 8 + 2 * ztg;
            *(float2*)&z_s[((kg * 64) + mt * 16 + zg) * 34 + col] =
                make_float2(acc[gate][0], acc[gate][1]);
            *(float2*)&z_s[((kg * 64) + mt * 16 + zg + 8) * 34 + col] =
                make_float2(acc[gate][2], acc[gate][3]);
        }
        __syncthreads();

        // ---- pointwise LSTM update + fragment-layout h store ----
        {
            int b = pb, hl = phl;
            float zi = rzx[0], zj = rzx[1], zf = rzx[2], zo = rzx[3];
#pragma unroll
            for (int g2 = 0; g2 < 4; g2++) {
                const float* zp = &z_s[(g2 * 64 + b) * 34];
                zi += zp[0 + hl];
                zj += zp[8 + hl];
                zf += zp[16 + hl];
                zo += zp[24 + hl];
            }

            float ig = fsig(zi);
            float jg = ftanh(zj);
            float fg = fsig(zf + 1.f);
            float og = fsig(zo);

            float cnew = fg * c_reg + ig * jg;
            float hnew = og * ftanh(cnew);
            c_reg = cnew;

            __nv_bfloat16 hhi = __float2bfloat16(hnew);
            __nv_bfloat16 hlo = __float2bfloat16(hnew - __bfloat162float(hhi));
            u32 vhi = (u32)__bfloat16_as_ushort(hhi);
            u32 vlo = (u32)__bfloat16_as_ushort(hlo);
            u32 phi = __shfl_down_sync(0xffffffffu, vhi, 1);
            u32 plo = __shfl_down_sync(0xffffffffu, vlo, 1);
            if ((hl & 1) == 0) {
                g_hfrag[dir][buf ^ 1][0][w_off] = vhi | (phi << 16);
                g_hfrag[dir][buf ^ 1][1][w_off] = vlo | (plo << 16);
            }
            out[((size_t)b * TT + tin) * (2 * HH) + dir * HH + h0 + hl] = hnew;
        }

        grid_barrier(dir, (unsigned)(t + 1));
    }
}

extern "C" void kernel_launch(void* const* d_in, const int* in_sizes, int n_in,
                              void* d_out, int out_size) {
    const float* x   = (const float*)d_in[0];
    const float* Wfw = (const float*)d_in[1];
    const float* bfw = (const float*)d_in[2];
    const float* Wbw = (const float*)d_in[3];
    const float* bbw = (const float*)d_in[4];
    float* out = (float*)d_out;

    static int attr_done = 0;
    if (!attr_done) {
        cudaFuncSetAttribute(lstm_persist, cudaFuncAttributeMaxDynamicSharedMemorySize,
                             PERSIST_SMEM);
        cudaFuncSetAttribute(pregemm_mma, cudaFuncAttributeMaxDynamicSharedMemorySize,
                             PG_SMEM);
        attr_done = 1;
    }

    prep_ab<<<(TT * BB * DD) / 256, 256>>>(x);
    prep_w<<<4096, 256>>>(Wfw, Wbw);

    pregemm_mma<<<dim3(G4H / 128, (TT * BB) / 128, 2), 256, PG_SMEM>>>(bfw, bbw);

    lstm_persist<<<dim3(64, 2), 512, PERSIST_SMEM>>>(out);
}